// round 6
// baseline (speedup 1.0000x reference)
#include <cuda_runtime.h>
#include <cuda_bf16.h>
#include <math.h>

#define T_STEPS 256
#define B_SZ    64
#define H_SZ    1024
#define O_SZ    1024
#define BH      (B_SZ * H_SZ)        // 65536
#define M_TOT   (T_STEPS * B_SZ)     // 16384
#define KSPLIT  8                    // recurrence k-split
#define NCTA    128
#define NLEAF   16
#define CTAS_PER_LEAF (NCTA / NLEAF) // 8
#define PAD     40                   // smem row stride (bf16) for big gemm tiles
#define RPAD    136                  // smem row stride (bf16) for rec tiles

typedef unsigned long long u64;
typedef unsigned int u32;

__device__ __forceinline__ u32 smem_u32(const void* p) {
    u32 a; asm("{ .reg .u64 t; cvta.to.shared.u64 t, %1; cvt.u32.u64 %0, t; }"
               : "=r"(a) : "l"(p));
    return a;
}

// ---- mma.sync helpers (plain PTX, validated on this build) -----------------
__device__ __forceinline__ void ldmx4(u32& r0, u32& r1, u32& r2, u32& r3, u32 a) {
    asm volatile("ldmatrix.sync.aligned.m8n8.x4.shared.b16 {%0,%1,%2,%3}, [%4];"
                 : "=r"(r0), "=r"(r1), "=r"(r2), "=r"(r3) : "r"(a));
}
__device__ __forceinline__ void mma16816(float* c, const u32* a, const u32* b) {
    asm volatile(
        "mma.sync.aligned.m16n8k16.row.col.f32.bf16.bf16.f32 "
        "{%0,%1,%2,%3}, {%4,%5,%6,%7}, {%8,%9}, {%0,%1,%2,%3};"
        : "+f"(c[0]), "+f"(c[1]), "+f"(c[2]), "+f"(c[3])
        : "r"(a[0]), "r"(a[1]), "r"(a[2]), "r"(a[3]), "r"(b[0]), "r"(b[1]));
}

// ---- scratch ---------------------------------------------------------------
__device__ float g_acc[(size_t)M_TOT * H_SZ];      // ix + bi + bh
__device__ __nv_bfloat16 g_A1hi[(size_t)M_TOT * H_SZ];
__device__ __nv_bfloat16 g_A1lo[(size_t)M_TOT * H_SZ];
__device__ __nv_bfloat16 g_hsbhi[(size_t)M_TOT * H_SZ];   // h states hi (bf16)
__device__ __nv_bfloat16 g_hsblo[(size_t)M_TOT * H_SZ];   // h states lo
__device__ __nv_bfloat16 g_h0hi[BH];
__device__ __nv_bfloat16 g_h0lo[BH];
__device__ __nv_bfloat16 g_WiThi[(size_t)H_SZ * H_SZ];    // [n][k]
__device__ __nv_bfloat16 g_WiTlo[(size_t)H_SZ * H_SZ];
__device__ __nv_bfloat16 g_WoThi[(size_t)H_SZ * O_SZ];
__device__ __nv_bfloat16 g_WoTlo[(size_t)H_SZ * O_SZ];
__device__ __nv_bfloat16 g_WhThi[(size_t)H_SZ * H_SZ];
__device__ __nv_bfloat16 g_WhTlo[(size_t)H_SZ * H_SZ];
__device__ float g_parts[(size_t)KSPLIT * BH];
__device__ float g_bias1[H_SZ];
// hierarchical barrier state: 128B-padded leaf counters, root, monotonic flag
__device__ unsigned g_leaf[2][NLEAF][32];
__device__ unsigned g_root[2][32];
__device__ unsigned g_flag[2];

// ---------------------------------------------------------------------------
// Prep kernels
// ---------------------------------------------------------------------------
__global__ void prep_bias(const float* __restrict__ bi, const float* __restrict__ bh) {
    int i = blockIdx.x * 256 + threadIdx.x;
    g_bias1[i] = bi[i] + bh[i];
}

template<int W>
__global__ void prep_transpose(const float* __restrict__ src) {
    __shared__ float ts[32][33];
    __nv_bfloat16* dhi = (W == 0) ? g_WiThi : (W == 1) ? g_WoThi : g_WhThi;
    __nv_bfloat16* dlo = (W == 0) ? g_WiTlo : (W == 1) ? g_WoTlo : g_WhTlo;
    int n0 = blockIdx.x * 32, k0 = blockIdx.y * 32;
    int tx = threadIdx.x & 31, ty = threadIdx.x >> 5;
#pragma unroll
    for (int i = 0; i < 4; i++)
        ts[ty + i * 8][tx] = src[(size_t)(k0 + ty + i * 8) * H_SZ + n0 + tx];
    __syncthreads();
#pragma unroll
    for (int i = 0; i < 4; i++) {
        int n = n0 + ty + i * 8;
        float v = ts[tx][ty + i * 8];
        __nv_bfloat16 h = __float2bfloat16(v);
        float r = v - __bfloat162float(h);
        dhi[(size_t)n * H_SZ + k0 + tx] = h;
        dlo[(size_t)n * H_SZ + k0 + tx] = __float2bfloat16(r);
    }
}

struct __align__(16) bf8 { __nv_bfloat16 v[8]; };

__global__ void prep_gather(const int* __restrict__ input, const float* __restrict__ emb) {
    size_t g = (size_t)blockIdx.x * 256 + threadIdx.x;
    size_t e = g * 8;
    int m = (int)(e >> 10), k = (int)(e & 1023);
    int t = m >> 6, b = m & 63;
    int row = input[b * T_STEPS + t];
    float4 v0 = *(const float4*)(emb + (size_t)row * H_SZ + k);
    float4 v1 = *(const float4*)(emb + (size_t)row * H_SZ + k + 4);
    float vv[8] = {v0.x, v0.y, v0.z, v0.w, v1.x, v1.y, v1.z, v1.w};
    bf8 hh, ll;
#pragma unroll
    for (int i = 0; i < 8; i++) {
        __nv_bfloat16 h = __float2bfloat16(vv[i]);
        hh.v[i] = h;
        ll.v[i] = __float2bfloat16(vv[i] - __bfloat162float(h));
    }
    *(bf8*)(g_A1hi + e) = hh;
    *(bf8*)(g_A1lo + e) = ll;
}

__global__ void prep_h0(const float* __restrict__ hidden0) {
    size_t e = ((size_t)blockIdx.x * 256 + threadIdx.x) * 4;
    float4 v = *(const float4*)(hidden0 + e);
    float vv[4] = {v.x, v.y, v.z, v.w};
    __nv_bfloat16 hh[4], ll[4];
#pragma unroll
    for (int i = 0; i < 4; i++) {
        hh[i] = __float2bfloat16(vv[i]);
        ll[i] = __float2bfloat16(vv[i] - __bfloat162float(hh[i]));
    }
    *(uint2*)(g_h0hi + e) = *(uint2*)hh;
    *(uint2*)(g_h0lo + e) = *(uint2*)ll;
}

// ---------------------------------------------------------------------------
// mma.sync big GEMM (proven): 128x128 CTA tile.
// ---------------------------------------------------------------------------
#define TILE_BF (128 * PAD)
#define SMEM_GEMM_BYTES (2 * 4 * TILE_BF * 2)

template<int MODE>
__global__ __launch_bounds__(256) void gemm_mma(const float* __restrict__ bias_ext,
                                                float* __restrict__ dst_ext)
{
    extern __shared__ __nv_bfloat16 sm[];
    const int tid = threadIdx.x, wid = tid >> 5, lane = tid & 31;
    const int nt = blockIdx.x, mt = blockIdx.y;
    const int wm = wid >> 1, wn = wid & 1;

    const __nv_bfloat16* Ahi = MODE ? g_hsbhi : g_A1hi;
    const __nv_bfloat16* Alo = MODE ? g_hsblo : g_A1lo;
    const __nv_bfloat16* Bhi = MODE ? g_WoThi : g_WiThi;
    const __nv_bfloat16* Blo = MODE ? g_WoTlo : g_WiTlo;
    const float* bias = MODE ? bias_ext : g_bias1;

    const __nv_bfloat16* srcA[2] = { Ahi + (size_t)mt * 128 * H_SZ,
                                     Alo + (size_t)mt * 128 * H_SZ };
    const __nv_bfloat16* srcB[2] = { Bhi + (size_t)nt * 128 * H_SZ,
                                     Blo + (size_t)nt * 128 * H_SZ };

    const int r0 = tid >> 2, q0 = tid & 3;
    const int r1 = (tid + 256) >> 2, q1 = tid & 3;

#pragma unroll
    for (int t4 = 0; t4 < 4; t4++) {
        const __nv_bfloat16* s = (t4 < 2) ? srcA[t4] : srcB[t4 - 2];
        __nv_bfloat16* d = sm + t4 * TILE_BF;
        *(uint4*)(d + r0 * PAD + q0 * 8) = *(const uint4*)(s + (size_t)r0 * H_SZ + q0 * 8);
        *(uint4*)(d + r1 * PAD + q1 * 8) = *(const uint4*)(s + (size_t)r1 * H_SZ + q1 * 8);
    }
    __syncthreads();

    float acc[2][8][4];
#pragma unroll
    for (int mi = 0; mi < 2; mi++)
#pragma unroll
        for (int j = 0; j < 8; j++)
#pragma unroll
            for (int v = 0; v < 4; v++) acc[mi][j][v] = 0.f;

    const u32 sbase = smem_u32(sm);
    const int a_row = lane & 15, a_kq = lane >> 4;
    const int b_nr = (lane >> 4) * 8 + (lane & 7), b_kq = (lane >> 3) & 1;

#pragma unroll 1
    for (int c = 0; c < 32; c++) {
        const int buf = c & 1;
        if (c < 31) {
            const int col0 = (c + 1) * 32;
#pragma unroll
            for (int t4 = 0; t4 < 4; t4++) {
                const __nv_bfloat16* s = ((t4 < 2) ? srcA[t4] : srcB[t4 - 2]) + col0;
                __nv_bfloat16* d = sm + ((buf ^ 1) * 4 + t4) * TILE_BF;
                *(uint4*)(d + r0 * PAD + q0 * 8) = *(const uint4*)(s + (size_t)r0 * H_SZ + q0 * 8);
                *(uint4*)(d + r1 * PAD + q1 * 8) = *(const uint4*)(s + (size_t)r1 * H_SZ + q1 * 8);
            }
        }

        const u32 bA = sbase + (u32)(buf * 4) * TILE_BF * 2;
#pragma unroll
        for (int s = 0; s < 2; s++) {
            const int kc0 = s * 16;
            u32 ahi[2][4], alo[2][4], bhi[8][2], blo[8][2];
#pragma unroll
            for (int mi = 0; mi < 2; mi++) {
                u32 off = (u32)((wm * 32 + mi * 16 + a_row) * PAD + kc0 + a_kq * 8) * 2;
                ldmx4(ahi[mi][0], ahi[mi][1], ahi[mi][2], ahi[mi][3], bA + 0 * TILE_BF * 2 + off);
                ldmx4(alo[mi][0], alo[mi][1], alo[mi][2], alo[mi][3], bA + 1 * TILE_BF * 2 + off);
            }
#pragma unroll
            for (int ni = 0; ni < 4; ni++) {
                u32 off = (u32)((wn * 64 + ni * 16 + b_nr) * PAD + kc0 + b_kq * 8) * 2;
                ldmx4(bhi[2*ni][0], bhi[2*ni][1], bhi[2*ni+1][0], bhi[2*ni+1][1],
                      bA + 2 * TILE_BF * 2 + off);
                ldmx4(blo[2*ni][0], blo[2*ni][1], blo[2*ni+1][0], blo[2*ni+1][1],
                      bA + 3 * TILE_BF * 2 + off);
            }
#pragma unroll
            for (int mi = 0; mi < 2; mi++)
#pragma unroll
                for (int j = 0; j < 8; j++) {
                    mma16816(acc[mi][j], ahi[mi], bhi[j]);
                    mma16816(acc[mi][j], ahi[mi], blo[j]);
                    mma16816(acc[mi][j], alo[mi], bhi[j]);
                }
        }
        __syncthreads();
    }

    const int gid = lane >> 2, qid = lane & 3;
#pragma unroll
    for (int mi = 0; mi < 2; mi++) {
#pragma unroll
        for (int j = 0; j < 8; j++) {
            int col = nt * 128 + wn * 64 + j * 8 + qid * 2;
            float2 bv = *(const float2*)(bias + col);
            int mA = mt * 128 + wm * 32 + mi * 16 + gid;
            int mB = mA + 8;
            float* dA; float* dB;
            if (MODE == 0) {
                dA = g_acc + (size_t)mA * H_SZ + col;
                dB = g_acc + (size_t)mB * H_SZ + col;
            } else {
                dA = dst_ext + ((size_t)(mA & 63) * T_STEPS + (mA >> 6)) * O_SZ + col;
                dB = dst_ext + ((size_t)(mB & 63) * T_STEPS + (mB >> 6)) * O_SZ + col;
            }
            *(float2*)dA = make_float2(acc[mi][j][0] + bv.x, acc[mi][j][1] + bv.y);
            *(float2*)dB = make_float2(acc[mi][j][2] + bv.x, acc[mi][j][3] + bv.y);
        }
    }
}

// ---------------------------------------------------------------------------
// Hierarchical grid barrier: leaf (8 CTAs) -> root (16 leaves) -> monotonic
// flag. Counters self-reset by their completing arriver; replay-safe.
// ---------------------------------------------------------------------------
__device__ __forceinline__ void grid_barrier(int slot) {
    __syncthreads();
    if (threadIdx.x == 0) {
        volatile unsigned* fl = &g_flag[slot];
        unsigned prev = *fl;                  // snapshot BEFORE arriving
        __threadfence();                      // publish this CTA's writes
        const int leaf = blockIdx.x & (NLEAF - 1);
        unsigned old = atomicAdd(&g_leaf[slot][leaf][0], 1u);
        if (old == CTAS_PER_LEAF - 1) {
            atomicExch(&g_leaf[slot][leaf][0], 0u);
            unsigned r = atomicAdd(&g_root[slot][0], 1u);
            if (r == NLEAF - 1) {
                atomicExch(&g_root[slot][0], 0u);
                __threadfence();
                atomicAdd(&g_flag[slot], 1u); // release
            }
        }
        while (*fl == prev) { }
        __threadfence();                      // acquire
    }
    __syncthreads();
}

// ---------------------------------------------------------------------------
// Persistent recurrence with mma.sync (proven R5 structure + acc prefetch).
// ---------------------------------------------------------------------------
#define R_WHI 0
#define R_WLO (64 * RPAD)
#define R_AHI (2 * 64 * RPAD)
#define R_ALO (3 * 64 * RPAD)
#define SMEM_REC_BYTES (4 * 64 * RPAD * 2)

__global__ __launch_bounds__(256) void rec_mma(float* __restrict__ hid_out)
{
    extern __shared__ __nv_bfloat16 rs[];
    const int tid = threadIdx.x, wid = tid >> 5, lane = tid & 31;
    const int ct  = blockIdx.x & 15;
    const int kc  = blockIdx.x >> 4;
    const int wm  = wid >> 1, wn = wid & 1;

    {
        const size_t base = (size_t)(ct * 64) * H_SZ + kc * 128;
#pragma unroll
        for (int i = 0; i < 4; i++) {
            int ch = tid + i * 256;
            int r  = ch >> 4;
            int co = (ch & 15) * 8;
            *(uint4*)(rs + R_WHI + r * RPAD + co) =
                *(const uint4*)(g_WhThi + base + (size_t)r * H_SZ + co);
            *(uint4*)(rs + R_WLO + r * RPAD + co) =
                *(const uint4*)(g_WhTlo + base + (size_t)r * H_SZ + co);
        }
    }

    const u32 sbase = smem_u32(rs);
    const int a_row = lane & 15, a_kq = lane >> 4;
    const int b_nr = (lane >> 4) * 8 + (lane & 7), b_kq = (lane >> 3) & 1;
    const int gid = lane >> 2, qid = lane & 3;
    const size_t red_e = (size_t)blockIdx.x * 512 + (size_t)tid * 4;  // reduce slice

#pragma unroll 1
    for (int t = 0; t < T_STEPS; t++) {
        const __nv_bfloat16* hhi = t ? (g_hsbhi + (size_t)(t - 1) * BH) : g_h0hi;
        const __nv_bfloat16* hlo = t ? (g_hsblo + (size_t)(t - 1) * BH) : g_h0lo;

        // prefetch pre-activation row for the reduce (barrier-independent)
        float4 aacc;
        if (tid < 128)
            aacc = *(const float4*)(g_acc + (size_t)t * BH + red_e);

        // load h slice: rows b = 0..63, cols k = kc*128 .. +128
#pragma unroll
        for (int i = 0; i < 4; i++) {
            int ch = tid + i * 256;
            int r  = ch >> 4;
            int co = (ch & 15) * 8;
            size_t off = (size_t)r * H_SZ + kc * 128 + co;
            *(uint4*)(rs + R_AHI + r * RPAD + co) = __ldcg((const uint4*)(hhi + off));
            *(uint4*)(rs + R_ALO + r * RPAD + co) = __ldcg((const uint4*)(hlo + off));
        }
        __syncthreads();

        float acc[4][4];
#pragma unroll
        for (int j = 0; j < 4; j++)
#pragma unroll
            for (int v = 0; v < 4; v++) acc[j][v] = 0.f;

#pragma unroll
        for (int ks = 0; ks < 8; ks++) {
            const int k0 = ks * 16;
            u32 ahi[4], alo[4], bhi[4][2], blo[4][2];
            {
                u32 off = (u32)((wm * 16 + a_row) * RPAD + k0 + a_kq * 8) * 2;
                ldmx4(ahi[0], ahi[1], ahi[2], ahi[3], sbase + R_AHI * 2 + off);
                ldmx4(alo[0], alo[1], alo[2], alo[3], sbase + R_ALO * 2 + off);
            }
#pragma unroll
            for (int ni = 0; ni < 2; ni++) {
                u32 off = (u32)((wn * 32 + ni * 16 + b_nr) * RPAD + k0 + b_kq * 8) * 2;
                ldmx4(bhi[2*ni][0], bhi[2*ni][1], bhi[2*ni+1][0], bhi[2*ni+1][1],
                      sbase + R_WHI * 2 + off);
                ldmx4(blo[2*ni][0], blo[2*ni][1], blo[2*ni+1][0], blo[2*ni+1][1],
                      sbase + R_WLO * 2 + off);
            }
#pragma unroll
            for (int j = 0; j < 4; j++) {
                mma16816(acc[j], ahi, bhi[j]);
                mma16816(acc[j], ahi, blo[j]);
                mma16816(acc[j], alo, bhi[j]);
            }
        }

        {
            float* p0 = g_parts + (size_t)kc * BH
                      + (size_t)(wm * 16 + gid) * H_SZ + ct * 64 + wn * 32;
            float* p1 = p0 + 8 * H_SZ;
#pragma unroll
            for (int j = 0; j < 4; j++) {
                *(float2*)(p0 + j * 8 + qid * 2) = make_float2(acc[j][0], acc[j][1]);
                *(float2*)(p1 + j * 8 + qid * 2) = make_float2(acc[j][2], acc[j][3]);
            }
        }

        grid_barrier(0);

        // fused reduce + tanh + bf16 hi/lo split
        if (tid < 128) {
            float4 a = aacc;
#pragma unroll
            for (int k2 = 0; k2 < KSPLIT; k2++) {
                float4 q = __ldcg((const float4*)(g_parts + (size_t)k2 * BH + red_e));
                a.x += q.x; a.y += q.y; a.z += q.z; a.w += q.w;
            }
            a.x = tanhf(a.x); a.y = tanhf(a.y); a.z = tanhf(a.z); a.w = tanhf(a.w);

            __nv_bfloat16 h0 = __float2bfloat16(a.x), h1 = __float2bfloat16(a.y);
            __nv_bfloat16 h2 = __float2bfloat16(a.z), h3 = __float2bfloat16(a.w);
            __nv_bfloat16 hh[4] = {h0, h1, h2, h3};
            __nv_bfloat16 ll[4] = {
                __float2bfloat16(a.x - __bfloat162float(h0)),
                __float2bfloat16(a.y - __bfloat162float(h1)),
                __float2bfloat16(a.z - __bfloat162float(h2)),
                __float2bfloat16(a.w - __bfloat162float(h3))};
            *(uint2*)(g_hsbhi + (size_t)t * BH + red_e) = *(uint2*)hh;
            *(uint2*)(g_hsblo + (size_t)t * BH + red_e) = *(uint2*)ll;

            if (hid_out && t == T_STEPS - 1)
                *(float4*)(hid_out + red_e) = a;
        }

        grid_barrier(1);
    }
}

// ---------------------------------------------------------------------------
extern "C" void kernel_launch(void* const* d_in, const int* in_sizes, int n_in,
                              void* d_out, int out_size)
{
    const int*   input   = (const int*)  d_in[0];
    const float* hidden0 = (const float*)d_in[1];
    const float* emb     = (const float*)d_in[2];
    const float* Wi      = (const float*)d_in[3];
    const float* bi      = (const float*)d_in[4];
    const float* Wh      = (const float*)d_in[5];
    const float* bh      = (const float*)d_in[6];
    const float* Wo      = (const float*)d_in[7];
    const float* bo      = (const float*)d_in[8];
    float* out = (float*)d_out;

    float* hid_out = (out_size >= M_TOT * O_SZ + BH) ? out + (size_t)M_TOT * O_SZ
                                                     : (float*)0;

    cudaFuncSetAttribute(gemm_mma<0>, cudaFuncAttributeMaxDynamicSharedMemorySize, SMEM_GEMM_BYTES);
    cudaFuncSetAttribute(gemm_mma<1>, cudaFuncAttributeMaxDynamicSharedMemorySize, SMEM_GEMM_BYTES);
    cudaFuncSetAttribute(rec_mma, cudaFuncAttributeMaxDynamicSharedMemorySize, SMEM_REC_BYTES);

    prep_bias<<<4, 256>>>(bi, bh);
    prep_transpose<0><<<dim3(32, 32), 256>>>(Wi);
    prep_transpose<1><<<dim3(32, 32), 256>>>(Wo);
    prep_transpose<2><<<dim3(32, 32), 256>>>(Wh);
    prep_h0<<<64, 256>>>(hidden0);
    prep_gather<<<8192, 256>>>(input, emb);

    gemm_mma<0><<<dim3(8, 128), 256, SMEM_GEMM_BYTES>>>((const float*)0, (float*)0);
    rec_mma<<<NCTA, 256, SMEM_REC_BYTES>>>(hid_out);
    gemm_mma<1><<<dim3(8, 128), 256, SMEM_GEMM_BYTES>>>(bo, out);
}

// round 7
// speedup vs baseline: 1.1293x; 1.1293x over previous
#include <cuda_runtime.h>
#include <cuda_bf16.h>
#include <math.h>

#define T_STEPS 256
#define B_SZ    64
#define H_SZ    1024
#define O_SZ    1024
#define BH      (B_SZ * H_SZ)        // 65536
#define M_TOT   (T_STEPS * B_SZ)     // 16384
#define KSPLIT  8                    // recurrence k-split == cluster size
#define NCTA    128
#define PAD     40                   // smem row stride (bf16) for big gemm tiles
#define RPAD    136                  // smem row stride (bf16) for rec tiles

typedef unsigned long long u64;
typedef unsigned int u32;

__device__ __forceinline__ u32 smem_u32(const void* p) {
    u32 a; asm("{ .reg .u64 t; cvta.to.shared.u64 t, %1; cvt.u32.u64 %0, t; }"
               : "=r"(a) : "l"(p));
    return a;
}

// ---- mma.sync helpers (plain PTX, validated on this build) -----------------
__device__ __forceinline__ void ldmx4(u32& r0, u32& r1, u32& r2, u32& r3, u32 a) {
    asm volatile("ldmatrix.sync.aligned.m8n8.x4.shared.b16 {%0,%1,%2,%3}, [%4];"
                 : "=r"(r0), "=r"(r1), "=r"(r2), "=r"(r3) : "r"(a));
}
__device__ __forceinline__ void mma16816(float* c, const u32* a, const u32* b) {
    asm volatile(
        "mma.sync.aligned.m16n8k16.row.col.f32.bf16.bf16.f32 "
        "{%0,%1,%2,%3}, {%4,%5,%6,%7}, {%8,%9}, {%0,%1,%2,%3};"
        : "+f"(c[0]), "+f"(c[1]), "+f"(c[2]), "+f"(c[3])
        : "r"(a[0]), "r"(a[1]), "r"(a[2]), "r"(a[3]), "r"(b[0]), "r"(b[1]));
}

// ---- scratch ---------------------------------------------------------------
__device__ float g_acc[(size_t)M_TOT * H_SZ];      // ix + bi + bh
__device__ __nv_bfloat16 g_A1hi[(size_t)M_TOT * H_SZ];
__device__ __nv_bfloat16 g_A1lo[(size_t)M_TOT * H_SZ];
__device__ __nv_bfloat16 g_hsbhi[(size_t)M_TOT * H_SZ];   // h states hi (bf16)
__device__ __nv_bfloat16 g_hsblo[(size_t)M_TOT * H_SZ];   // h states lo
__device__ __nv_bfloat16 g_h0hi[BH];
__device__ __nv_bfloat16 g_h0lo[BH];
__device__ __nv_bfloat16 g_WiThi[(size_t)H_SZ * H_SZ];    // [n][k]
__device__ __nv_bfloat16 g_WiTlo[(size_t)H_SZ * H_SZ];
__device__ __nv_bfloat16 g_WoThi[(size_t)H_SZ * O_SZ];
__device__ __nv_bfloat16 g_WoTlo[(size_t)H_SZ * O_SZ];
__device__ __nv_bfloat16 g_WhThi[(size_t)H_SZ * H_SZ];
__device__ __nv_bfloat16 g_WhTlo[(size_t)H_SZ * H_SZ];
__device__ float g_parts[(size_t)KSPLIT * BH];
__device__ float g_bias1[H_SZ];
__device__ unsigned g_cnt[2];      // flat barrier counter
__device__ unsigned g_flag[2];     // monotonic release flag

// ---------------------------------------------------------------------------
// Prep kernels
// ---------------------------------------------------------------------------
__global__ void prep_bias(const float* __restrict__ bi, const float* __restrict__ bh) {
    int i = blockIdx.x * 256 + threadIdx.x;
    g_bias1[i] = bi[i] + bh[i];
}

template<int W>
__global__ void prep_transpose(const float* __restrict__ src) {
    __shared__ float ts[32][33];
    __nv_bfloat16* dhi = (W == 0) ? g_WiThi : (W == 1) ? g_WoThi : g_WhThi;
    __nv_bfloat16* dlo = (W == 0) ? g_WiTlo : (W == 1) ? g_WoTlo : g_WhTlo;
    int n0 = blockIdx.x * 32, k0 = blockIdx.y * 32;
    int tx = threadIdx.x & 31, ty = threadIdx.x >> 5;
#pragma unroll
    for (int i = 0; i < 4; i++)
        ts[ty + i * 8][tx] = src[(size_t)(k0 + ty + i * 8) * H_SZ + n0 + tx];
    __syncthreads();
#pragma unroll
    for (int i = 0; i < 4; i++) {
        int n = n0 + ty + i * 8;
        float v = ts[tx][ty + i * 8];
        __nv_bfloat16 h = __float2bfloat16(v);
        float r = v - __bfloat162float(h);
        dhi[(size_t)n * H_SZ + k0 + tx] = h;
        dlo[(size_t)n * H_SZ + k0 + tx] = __float2bfloat16(r);
    }
}

struct __align__(16) bf8 { __nv_bfloat16 v[8]; };

__global__ void prep_gather(const int* __restrict__ input, const float* __restrict__ emb) {
    size_t g = (size_t)blockIdx.x * 256 + threadIdx.x;
    size_t e = g * 8;
    int m = (int)(e >> 10), k = (int)(e & 1023);
    int t = m >> 6, b = m & 63;
    int row = input[b * T_STEPS + t];
    float4 v0 = *(const float4*)(emb + (size_t)row * H_SZ + k);
    float4 v1 = *(const float4*)(emb + (size_t)row * H_SZ + k + 4);
    float vv[8] = {v0.x, v0.y, v0.z, v0.w, v1.x, v1.y, v1.z, v1.w};
    bf8 hh, ll;
#pragma unroll
    for (int i = 0; i < 8; i++) {
        __nv_bfloat16 h = __float2bfloat16(vv[i]);
        hh.v[i] = h;
        ll.v[i] = __float2bfloat16(vv[i] - __bfloat162float(h));
    }
    *(bf8*)(g_A1hi + e) = hh;
    *(bf8*)(g_A1lo + e) = ll;
}

__global__ void prep_h0(const float* __restrict__ hidden0) {
    size_t e = ((size_t)blockIdx.x * 256 + threadIdx.x) * 4;
    float4 v = *(const float4*)(hidden0 + e);
    float vv[4] = {v.x, v.y, v.z, v.w};
    __nv_bfloat16 hh[4], ll[4];
#pragma unroll
    for (int i = 0; i < 4; i++) {
        hh[i] = __float2bfloat16(vv[i]);
        ll[i] = __float2bfloat16(vv[i] - __bfloat162float(hh[i]));
    }
    *(uint2*)(g_h0hi + e) = *(uint2*)hh;
    *(uint2*)(g_h0lo + e) = *(uint2*)ll;
}

// ---------------------------------------------------------------------------
// mma.sync big GEMM (proven): 128x128 CTA tile.
// ---------------------------------------------------------------------------
#define TILE_BF (128 * PAD)
#define SMEM_GEMM_BYTES (2 * 4 * TILE_BF * 2)

template<int MODE>
__global__ __launch_bounds__(256) void gemm_mma(const float* __restrict__ bias_ext,
                                                float* __restrict__ dst_ext)
{
    extern __shared__ __nv_bfloat16 sm[];
    const int tid = threadIdx.x, wid = tid >> 5, lane = tid & 31;
    const int nt = blockIdx.x, mt = blockIdx.y;
    const int wm = wid >> 1, wn = wid & 1;

    const __nv_bfloat16* Ahi = MODE ? g_hsbhi : g_A1hi;
    const __nv_bfloat16* Alo = MODE ? g_hsblo : g_A1lo;
    const __nv_bfloat16* Bhi = MODE ? g_WoThi : g_WiThi;
    const __nv_bfloat16* Blo = MODE ? g_WoTlo : g_WiTlo;
    const float* bias = MODE ? bias_ext : g_bias1;

    const __nv_bfloat16* srcA[2] = { Ahi + (size_t)mt * 128 * H_SZ,
                                     Alo + (size_t)mt * 128 * H_SZ };
    const __nv_bfloat16* srcB[2] = { Bhi + (size_t)nt * 128 * H_SZ,
                                     Blo + (size_t)nt * 128 * H_SZ };

    const int r0 = tid >> 2, q0 = tid & 3;
    const int r1 = (tid + 256) >> 2, q1 = tid & 3;

#pragma unroll
    for (int t4 = 0; t4 < 4; t4++) {
        const __nv_bfloat16* s = (t4 < 2) ? srcA[t4] : srcB[t4 - 2];
        __nv_bfloat16* d = sm + t4 * TILE_BF;
        *(uint4*)(d + r0 * PAD + q0 * 8) = *(const uint4*)(s + (size_t)r0 * H_SZ + q0 * 8);
        *(uint4*)(d + r1 * PAD + q1 * 8) = *(const uint4*)(s + (size_t)r1 * H_SZ + q1 * 8);
    }
    __syncthreads();

    float acc[2][8][4];
#pragma unroll
    for (int mi = 0; mi < 2; mi++)
#pragma unroll
        for (int j = 0; j < 8; j++)
#pragma unroll
            for (int v = 0; v < 4; v++) acc[mi][j][v] = 0.f;

    const u32 sbase = smem_u32(sm);
    const int a_row = lane & 15, a_kq = lane >> 4;
    const int b_nr = (lane >> 4) * 8 + (lane & 7), b_kq = (lane >> 3) & 1;

#pragma unroll 1
    for (int c = 0; c < 32; c++) {
        const int buf = c & 1;
        if (c < 31) {
            const int col0 = (c + 1) * 32;
#pragma unroll
            for (int t4 = 0; t4 < 4; t4++) {
                const __nv_bfloat16* s = ((t4 < 2) ? srcA[t4] : srcB[t4 - 2]) + col0;
                __nv_bfloat16* d = sm + ((buf ^ 1) * 4 + t4) * TILE_BF;
                *(uint4*)(d + r0 * PAD + q0 * 8) = *(const uint4*)(s + (size_t)r0 * H_SZ + q0 * 8);
                *(uint4*)(d + r1 * PAD + q1 * 8) = *(const uint4*)(s + (size_t)r1 * H_SZ + q1 * 8);
            }
        }

        const u32 bA = sbase + (u32)(buf * 4) * TILE_BF * 2;
#pragma unroll
        for (int s = 0; s < 2; s++) {
            const int kc0 = s * 16;
            u32 ahi[2][4], alo[2][4], bhi[8][2], blo[8][2];
#pragma unroll
            for (int mi = 0; mi < 2; mi++) {
                u32 off = (u32)((wm * 32 + mi * 16 + a_row) * PAD + kc0 + a_kq * 8) * 2;
                ldmx4(ahi[mi][0], ahi[mi][1], ahi[mi][2], ahi[mi][3], bA + 0 * TILE_BF * 2 + off);
                ldmx4(alo[mi][0], alo[mi][1], alo[mi][2], alo[mi][3], bA + 1 * TILE_BF * 2 + off);
            }
#pragma unroll
            for (int ni = 0; ni < 4; ni++) {
                u32 off = (u32)((wn * 64 + ni * 16 + b_nr) * PAD + kc0 + b_kq * 8) * 2;
                ldmx4(bhi[2*ni][0], bhi[2*ni][1], bhi[2*ni+1][0], bhi[2*ni+1][1],
                      bA + 2 * TILE_BF * 2 + off);
                ldmx4(blo[2*ni][0], blo[2*ni][1], blo[2*ni+1][0], blo[2*ni+1][1],
                      bA + 3 * TILE_BF * 2 + off);
            }
#pragma unroll
            for (int mi = 0; mi < 2; mi++)
#pragma unroll
                for (int j = 0; j < 8; j++) {
                    mma16816(acc[mi][j], ahi[mi], bhi[j]);
                    mma16816(acc[mi][j], ahi[mi], blo[j]);
                    mma16816(acc[mi][j], alo[mi], bhi[j]);
                }
        }
        __syncthreads();
    }

    const int gid = lane >> 2, qid = lane & 3;
#pragma unroll
    for (int mi = 0; mi < 2; mi++) {
#pragma unroll
        for (int j = 0; j < 8; j++) {
            int col = nt * 128 + wn * 64 + j * 8 + qid * 2;
            float2 bv = *(const float2*)(bias + col);
            int mA = mt * 128 + wm * 32 + mi * 16 + gid;
            int mB = mA + 8;
            float* dA; float* dB;
            if (MODE == 0) {
                dA = g_acc + (size_t)mA * H_SZ + col;
                dB = g_acc + (size_t)mB * H_SZ + col;
            } else {
                dA = dst_ext + ((size_t)(mA & 63) * T_STEPS + (mA >> 6)) * O_SZ + col;
                dB = dst_ext + ((size_t)(mB & 63) * T_STEPS + (mB >> 6)) * O_SZ + col;
            }
            *(float2*)dA = make_float2(acc[mi][j][0] + bv.x, acc[mi][j][1] + bv.y);
            *(float2*)dB = make_float2(acc[mi][j][2] + bv.x, acc[mi][j][3] + bv.y);
        }
    }
}

// ---------------------------------------------------------------------------
// Flat grid barrier (R5-proven: monotonic flag, self-resetting counter)
// ---------------------------------------------------------------------------
__device__ __forceinline__ void grid_barrier(int slot) {
    __syncthreads();
    if (threadIdx.x == 0) {
        volatile unsigned* fl = &g_flag[slot];
        unsigned prev = *fl;
        __threadfence();
        unsigned old = atomicAdd(&g_cnt[slot], 1u);
        if (old == NCTA - 1) {
            atomicExch(&g_cnt[slot], 0u);
            __threadfence();
            atomicAdd(&g_flag[slot], 1u);
        } else {
            while (*fl == prev) { }
        }
        __threadfence();
    }
    __syncthreads();
}

// ---------------------------------------------------------------------------
// Persistent recurrence, clustered: cluster = 8 CTAs sharing output tile ct.
// ct = blockIdx.x >> 3 (n-tile of 64), kc = blockIdx.x & 7 (k-chunk of 128).
// Per step: h load -> mma -> partial store -> CLUSTER sync -> in-cluster
// reduce (rows kc*8..+8, cols ct*64..+64) + tanh + split -> ONE grid barrier.
// ---------------------------------------------------------------------------
#define R_WHI 0
#define R_WLO (64 * RPAD)
#define R_AHI (2 * 64 * RPAD)
#define R_ALO (3 * 64 * RPAD)
#define SMEM_REC_BYTES (4 * 64 * RPAD * 2)

__global__ __launch_bounds__(256) __cluster_dims__(KSPLIT, 1, 1)
void rec_mma(float* __restrict__ hid_out)
{
    extern __shared__ __nv_bfloat16 rs[];
    const int tid = threadIdx.x, wid = tid >> 5, lane = tid & 31;
    const int ct  = blockIdx.x >> 3;
    const int kc  = blockIdx.x & 7;
    const int wm  = wid >> 1, wn = wid & 1;

    // one-time Wh tile load: rows n = ct*64 .. +64, cols k = kc*128 .. +128
    {
        const size_t base = (size_t)(ct * 64) * H_SZ + kc * 128;
#pragma unroll
        for (int i = 0; i < 4; i++) {
            int ch = tid + i * 256;
            int r  = ch >> 4;
            int co = (ch & 15) * 8;
            *(uint4*)(rs + R_WHI + r * RPAD + co) =
                *(const uint4*)(g_WhThi + base + (size_t)r * H_SZ + co);
            *(uint4*)(rs + R_WLO + r * RPAD + co) =
                *(const uint4*)(g_WhTlo + base + (size_t)r * H_SZ + co);
        }
    }

    const u32 sbase = smem_u32(rs);
    const int a_row = lane & 15, a_kq = lane >> 4;
    const int b_nr = (lane >> 4) * 8 + (lane & 7), b_kq = (lane >> 3) & 1;
    const int gid = lane >> 2, qid = lane & 3;

    // reduce mapping: this CTA reduces rows kc*8 + (tid>>5), cols ct*64 + (tid&31)*2
    const int red_row = kc * 8 + (tid >> 5);
    const size_t red_off = (size_t)red_row * H_SZ + ct * 64 + (tid & 31) * 2;

#pragma unroll 1
    for (int t = 0; t < T_STEPS; t++) {
        const __nv_bfloat16* hhi = t ? (g_hsbhi + (size_t)(t - 1) * BH) : g_h0hi;
        const __nv_bfloat16* hlo = t ? (g_hsblo + (size_t)(t - 1) * BH) : g_h0lo;

        // prefetch pre-activation for the reduce (read-only, barrier-independent)
        float2 aacc = *(const float2*)(g_acc + (size_t)t * BH + red_off);

        // load h slice: rows b = 0..63, cols k = kc*128 .. +128
#pragma unroll
        for (int i = 0; i < 4; i++) {
            int ch = tid + i * 256;
            int r  = ch >> 4;
            int co = (ch & 15) * 8;
            size_t off = (size_t)r * H_SZ + kc * 128 + co;
            *(uint4*)(rs + R_AHI + r * RPAD + co) = __ldcg((const uint4*)(hhi + off));
            *(uint4*)(rs + R_ALO + r * RPAD + co) = __ldcg((const uint4*)(hlo + off));
        }
        __syncthreads();

        float acc[4][4];
#pragma unroll
        for (int j = 0; j < 4; j++)
#pragma unroll
            for (int v = 0; v < 4; v++) acc[j][v] = 0.f;

#pragma unroll
        for (int ks = 0; ks < 8; ks++) {
            const int k0 = ks * 16;
            u32 ahi[4], alo[4], bhi[4][2], blo[4][2];
            {
                u32 off = (u32)((wm * 16 + a_row) * RPAD + k0 + a_kq * 8) * 2;
                ldmx4(ahi[0], ahi[1], ahi[2], ahi[3], sbase + R_AHI * 2 + off);
                ldmx4(alo[0], alo[1], alo[2], alo[3], sbase + R_ALO * 2 + off);
            }
#pragma unroll
            for (int ni = 0; ni < 2; ni++) {
                u32 off = (u32)((wn * 32 + ni * 16 + b_nr) * RPAD + k0 + b_kq * 8) * 2;
                ldmx4(bhi[2*ni][0], bhi[2*ni][1], bhi[2*ni+1][0], bhi[2*ni+1][1],
                      sbase + R_WHI * 2 + off);
                ldmx4(blo[2*ni][0], blo[2*ni][1], blo[2*ni+1][0], blo[2*ni+1][1],
                      sbase + R_WLO * 2 + off);
            }
#pragma unroll
            for (int j = 0; j < 4; j++) {
                mma16816(acc[j], ahi, bhi[j]);
                mma16816(acc[j], ahi, blo[j]);
                mma16816(acc[j], alo, bhi[j]);
            }
        }

        // partial store: rows wm*16+gid(+8), cols ct*64 + wn*32 + j*8 + qid*2
        {
            float* p0 = g_parts + (size_t)kc * BH
                      + (size_t)(wm * 16 + gid) * H_SZ + ct * 64 + wn * 32;
            float* p1 = p0 + 8 * H_SZ;
#pragma unroll
            for (int j = 0; j < 4; j++) {
                *(float2*)(p0 + j * 8 + qid * 2) = make_float2(acc[j][0], acc[j][1]);
                *(float2*)(p1 + j * 8 + qid * 2) = make_float2(acc[j][2], acc[j][3]);
            }
        }

        // cluster-local barrier: partials of this ct-tile are produced only by
        // this cluster's 8 CTAs; reduce reads only those.
        __threadfence();
        asm volatile("barrier.cluster.arrive.aligned;" ::: "memory");
        asm volatile("barrier.cluster.wait.aligned;"   ::: "memory");

        // in-cluster reduce + tanh + bf16 hi/lo split (all 256 threads, 2 els)
        {
            float2 a = aacc;
#pragma unroll
            for (int p = 0; p < KSPLIT; p++) {
                float2 q = __ldcg((const float2*)(g_parts + (size_t)p * BH + red_off));
                a.x += q.x; a.y += q.y;
            }
            a.x = tanhf(a.x); a.y = tanhf(a.y);

            __nv_bfloat16 h0 = __float2bfloat16(a.x), h1 = __float2bfloat16(a.y);
            __nv_bfloat16 hh[2] = {h0, h1};
            __nv_bfloat16 ll[2] = {
                __float2bfloat16(a.x - __bfloat162float(h0)),
                __float2bfloat16(a.y - __bfloat162float(h1))};
            *(u32*)(g_hsbhi + (size_t)t * BH + red_off) = *(u32*)hh;
            *(u32*)(g_hsblo + (size_t)t * BH + red_off) = *(u32*)ll;

            if (hid_out && t == T_STEPS - 1)
                *(float2*)(hid_out + red_off) = a;
        }

        // single grid barrier: h(t) fully written before anyone reads it
        grid_barrier(t & 1);
    }
}

// ---------------------------------------------------------------------------
extern "C" void kernel_launch(void* const* d_in, const int* in_sizes, int n_in,
                              void* d_out, int out_size)
{
    const int*   input   = (const int*)  d_in[0];
    const float* hidden0 = (const float*)d_in[1];
    const float* emb     = (const float*)d_in[2];
    const float* Wi      = (const float*)d_in[3];
    const float* bi      = (const float*)d_in[4];
    const float* Wh      = (const float*)d_in[5];
    const float* bh      = (const float*)d_in[6];
    const float* Wo      = (const float*)d_in[7];
    const float* bo      = (const float*)d_in[8];
    float* out = (float*)d_out;

    float* hid_out = (out_size >= M_TOT * O_SZ + BH) ? out + (size_t)M_TOT * O_SZ
                                                     : (float*)0;

    cudaFuncSetAttribute(gemm_mma<0>, cudaFuncAttributeMaxDynamicSharedMemorySize, SMEM_GEMM_BYTES);
    cudaFuncSetAttribute(gemm_mma<1>, cudaFuncAttributeMaxDynamicSharedMemorySize, SMEM_GEMM_BYTES);
    cudaFuncSetAttribute(rec_mma, cudaFuncAttributeMaxDynamicSharedMemorySize, SMEM_REC_BYTES);

    prep_bias<<<4, 256>>>(bi, bh);
    prep_transpose<0><<<dim3(32, 32), 256>>>(Wi);
    prep_transpose<1><<<dim3(32, 32), 256>>>(Wo);
    prep_transpose<2><<<dim3(32, 32), 256>>>(Wh);
    prep_h0<<<64, 256>>>(hidden0);
    prep_gather<<<8192, 256>>>(input, emb);

    gemm_mma<0><<<dim3(8, 128), 256, SMEM_GEMM_BYTES>>>((const float*)0, (float*)0);
    rec_mma<<<NCTA, 256, SMEM_REC_BYTES>>>(hid_out);
    gemm_mma<1><<<dim3(8, 128), 256, SMEM_GEMM_BYTES>>>(bo, out);
}

// round 8
// speedup vs baseline: 1.1382x; 1.0079x over previous
#include <cuda_runtime.h>
#include <cuda_bf16.h>
#include <math.h>

#define T_STEPS 256
#define B_SZ    64
#define H_SZ    1024
#define O_SZ    1024
#define BH      (B_SZ * H_SZ)        // 65536
#define M_TOT   (T_STEPS * B_SZ)     // 16384
#define KSPLIT  8                    // recurrence k-split == cluster size
#define NCTA    128
#define PAD     40                   // smem row stride (bf16) for big gemm tiles
#define RPAD    136                  // smem row stride (bf16) for rec tiles

typedef unsigned long long u64;
typedef unsigned int u32;

__device__ __forceinline__ u32 smem_u32(const void* p) {
    u32 a; asm("{ .reg .u64 t; cvta.to.shared.u64 t, %1; cvt.u32.u64 %0, t; }"
               : "=r"(a) : "l"(p));
    return a;
}

// ---- mma.sync helpers (plain PTX, validated on this build) -----------------
__device__ __forceinline__ void ldmx4(u32& r0, u32& r1, u32& r2, u32& r3, u32 a) {
    asm volatile("ldmatrix.sync.aligned.m8n8.x4.shared.b16 {%0,%1,%2,%3}, [%4];"
                 : "=r"(r0), "=r"(r1), "=r"(r2), "=r"(r3) : "r"(a));
}
__device__ __forceinline__ void mma16816(float* c, const u32* a, const u32* b) {
    asm volatile(
        "mma.sync.aligned.m16n8k16.row.col.f32.bf16.bf16.f32 "
        "{%0,%1,%2,%3}, {%4,%5,%6,%7}, {%8,%9}, {%0,%1,%2,%3};"
        : "+f"(c[0]), "+f"(c[1]), "+f"(c[2]), "+f"(c[3])
        : "r"(a[0]), "r"(a[1]), "r"(a[2]), "r"(a[3]), "r"(b[0]), "r"(b[1]));
}

// ---- scratch ---------------------------------------------------------------
__device__ float g_acc[(size_t)M_TOT * H_SZ];      // ix + bi + bh
__device__ __nv_bfloat16 g_A1hi[(size_t)M_TOT * H_SZ];
__device__ __nv_bfloat16 g_A1lo[(size_t)M_TOT * H_SZ];
__device__ __nv_bfloat16 g_hsbhi[(size_t)M_TOT * H_SZ];   // h states hi (bf16)
__device__ __nv_bfloat16 g_hsblo[(size_t)M_TOT * H_SZ];   // h states lo
__device__ __nv_bfloat16 g_h0hi[BH];
__device__ __nv_bfloat16 g_h0lo[BH];
__device__ __nv_bfloat16 g_WiThi[(size_t)H_SZ * H_SZ];    // [n][k]
__device__ __nv_bfloat16 g_WiTlo[(size_t)H_SZ * H_SZ];
__device__ __nv_bfloat16 g_WoThi[(size_t)H_SZ * O_SZ];
__device__ __nv_bfloat16 g_WoTlo[(size_t)H_SZ * O_SZ];
__device__ __nv_bfloat16 g_WhThi[(size_t)H_SZ * H_SZ];
__device__ __nv_bfloat16 g_WhTlo[(size_t)H_SZ * H_SZ];
__device__ float g_parts[2][(size_t)KSPLIT * BH];  // double-buffered by t&1
__device__ float g_bias1[H_SZ];
__device__ unsigned g_cnt[2];      // flat barrier counter (end-of-kernel only)
__device__ unsigned g_flag[2];     // monotonic release flag
__device__ u32 g_stepf[16][8];     // per-(chunk ct, sub kc) progress flags

// ---------------------------------------------------------------------------
// Prep kernels
// ---------------------------------------------------------------------------
__global__ void prep_bias(const float* __restrict__ bi, const float* __restrict__ bh) {
    int i = blockIdx.x * 256 + threadIdx.x;
    g_bias1[i] = bi[i] + bh[i];
}

template<int W>
__global__ void prep_transpose(const float* __restrict__ src) {
    __shared__ float ts[32][33];
    __nv_bfloat16* dhi = (W == 0) ? g_WiThi : (W == 1) ? g_WoThi : g_WhThi;
    __nv_bfloat16* dlo = (W == 0) ? g_WiTlo : (W == 1) ? g_WoTlo : g_WhTlo;
    int n0 = blockIdx.x * 32, k0 = blockIdx.y * 32;
    int tx = threadIdx.x & 31, ty = threadIdx.x >> 5;
#pragma unroll
    for (int i = 0; i < 4; i++)
        ts[ty + i * 8][tx] = src[(size_t)(k0 + ty + i * 8) * H_SZ + n0 + tx];
    __syncthreads();
#pragma unroll
    for (int i = 0; i < 4; i++) {
        int n = n0 + ty + i * 8;
        float v = ts[tx][ty + i * 8];
        __nv_bfloat16 h = __float2bfloat16(v);
        float r = v - __bfloat162float(h);
        dhi[(size_t)n * H_SZ + k0 + tx] = h;
        dlo[(size_t)n * H_SZ + k0 + tx] = __float2bfloat16(r);
    }
}

struct __align__(16) bf8 { __nv_bfloat16 v[8]; };

__global__ void prep_gather(const int* __restrict__ input, const float* __restrict__ emb) {
    size_t g = (size_t)blockIdx.x * 256 + threadIdx.x;
    size_t e = g * 8;
    int m = (int)(e >> 10), k = (int)(e & 1023);
    int t = m >> 6, b = m & 63;
    int row = input[b * T_STEPS + t];
    float4 v0 = *(const float4*)(emb + (size_t)row * H_SZ + k);
    float4 v1 = *(const float4*)(emb + (size_t)row * H_SZ + k + 4);
    float vv[8] = {v0.x, v0.y, v0.z, v0.w, v1.x, v1.y, v1.z, v1.w};
    bf8 hh, ll;
#pragma unroll
    for (int i = 0; i < 8; i++) {
        __nv_bfloat16 h = __float2bfloat16(vv[i]);
        hh.v[i] = h;
        ll.v[i] = __float2bfloat16(vv[i] - __bfloat162float(h));
    }
    *(bf8*)(g_A1hi + e) = hh;
    *(bf8*)(g_A1lo + e) = ll;
}

__global__ void prep_h0(const float* __restrict__ hidden0) {
    size_t e = ((size_t)blockIdx.x * 256 + threadIdx.x) * 4;
    float4 v = *(const float4*)(hidden0 + e);
    float vv[4] = {v.x, v.y, v.z, v.w};
    __nv_bfloat16 hh[4], ll[4];
#pragma unroll
    for (int i = 0; i < 4; i++) {
        hh[i] = __float2bfloat16(vv[i]);
        ll[i] = __float2bfloat16(vv[i] - __bfloat162float(hh[i]));
    }
    *(uint2*)(g_h0hi + e) = *(uint2*)hh;
    *(uint2*)(g_h0lo + e) = *(uint2*)ll;
}

// ---------------------------------------------------------------------------
// mma.sync big GEMM (proven): 128x128 CTA tile.
// ---------------------------------------------------------------------------
#define TILE_BF (128 * PAD)
#define SMEM_GEMM_BYTES (2 * 4 * TILE_BF * 2)

template<int MODE>
__global__ __launch_bounds__(256) void gemm_mma(const float* __restrict__ bias_ext,
                                                float* __restrict__ dst_ext)
{
    extern __shared__ __nv_bfloat16 sm[];
    const int tid = threadIdx.x, wid = tid >> 5, lane = tid & 31;
    const int nt = blockIdx.x, mt = blockIdx.y;
    const int wm = wid >> 1, wn = wid & 1;

    const __nv_bfloat16* Ahi = MODE ? g_hsbhi : g_A1hi;
    const __nv_bfloat16* Alo = MODE ? g_hsblo : g_A1lo;
    const __nv_bfloat16* Bhi = MODE ? g_WoThi : g_WiThi;
    const __nv_bfloat16* Blo = MODE ? g_WoTlo : g_WiTlo;
    const float* bias = MODE ? bias_ext : g_bias1;

    const __nv_bfloat16* srcA[2] = { Ahi + (size_t)mt * 128 * H_SZ,
                                     Alo + (size_t)mt * 128 * H_SZ };
    const __nv_bfloat16* srcB[2] = { Bhi + (size_t)nt * 128 * H_SZ,
                                     Blo + (size_t)nt * 128 * H_SZ };

    const int r0 = tid >> 2, q0 = tid & 3;
    const int r1 = (tid + 256) >> 2, q1 = tid & 3;

#pragma unroll
    for (int t4 = 0; t4 < 4; t4++) {
        const __nv_bfloat16* s = (t4 < 2) ? srcA[t4] : srcB[t4 - 2];
        __nv_bfloat16* d = sm + t4 * TILE_BF;
        *(uint4*)(d + r0 * PAD + q0 * 8) = *(const uint4*)(s + (size_t)r0 * H_SZ + q0 * 8);
        *(uint4*)(d + r1 * PAD + q1 * 8) = *(const uint4*)(s + (size_t)r1 * H_SZ + q1 * 8);
    }
    __syncthreads();

    float acc[2][8][4];
#pragma unroll
    for (int mi = 0; mi < 2; mi++)
#pragma unroll
        for (int j = 0; j < 8; j++)
#pragma unroll
            for (int v = 0; v < 4; v++) acc[mi][j][v] = 0.f;

    const u32 sbase = smem_u32(sm);
    const int a_row = lane & 15, a_kq = lane >> 4;
    const int b_nr = (lane >> 4) * 8 + (lane & 7), b_kq = (lane >> 3) & 1;

#pragma unroll 1
    for (int c = 0; c < 32; c++) {
        const int buf = c & 1;
        if (c < 31) {
            const int col0 = (c + 1) * 32;
#pragma unroll
            for (int t4 = 0; t4 < 4; t4++) {
                const __nv_bfloat16* s = ((t4 < 2) ? srcA[t4] : srcB[t4 - 2]) + col0;
                __nv_bfloat16* d = sm + ((buf ^ 1) * 4 + t4) * TILE_BF;
                *(uint4*)(d + r0 * PAD + q0 * 8) = *(const uint4*)(s + (size_t)r0 * H_SZ + q0 * 8);
                *(uint4*)(d + r1 * PAD + q1 * 8) = *(const uint4*)(s + (size_t)r1 * H_SZ + q1 * 8);
            }
        }

        const u32 bA = sbase + (u32)(buf * 4) * TILE_BF * 2;
#pragma unroll
        for (int s = 0; s < 2; s++) {
            const int kc0 = s * 16;
            u32 ahi[2][4], alo[2][4], bhi[8][2], blo[8][2];
#pragma unroll
            for (int mi = 0; mi < 2; mi++) {
                u32 off = (u32)((wm * 32 + mi * 16 + a_row) * PAD + kc0 + a_kq * 8) * 2;
                ldmx4(ahi[mi][0], ahi[mi][1], ahi[mi][2], ahi[mi][3], bA + 0 * TILE_BF * 2 + off);
                ldmx4(alo[mi][0], alo[mi][1], alo[mi][2], alo[mi][3], bA + 1 * TILE_BF * 2 + off);
            }
#pragma unroll
            for (int ni = 0; ni < 4; ni++) {
                u32 off = (u32)((wn * 64 + ni * 16 + b_nr) * PAD + kc0 + b_kq * 8) * 2;
                ldmx4(bhi[2*ni][0], bhi[2*ni][1], bhi[2*ni+1][0], bhi[2*ni+1][1],
                      bA + 2 * TILE_BF * 2 + off);
                ldmx4(blo[2*ni][0], blo[2*ni][1], blo[2*ni+1][0], blo[2*ni+1][1],
                      bA + 3 * TILE_BF * 2 + off);
            }
#pragma unroll
            for (int mi = 0; mi < 2; mi++)
#pragma unroll
                for (int j = 0; j < 8; j++) {
                    mma16816(acc[mi][j], ahi[mi], bhi[j]);
                    mma16816(acc[mi][j], ahi[mi], blo[j]);
                    mma16816(acc[mi][j], alo[mi], bhi[j]);
                }
        }
        __syncthreads();
    }

    const int gid = lane >> 2, qid = lane & 3;
#pragma unroll
    for (int mi = 0; mi < 2; mi++) {
#pragma unroll
        for (int j = 0; j < 8; j++) {
            int col = nt * 128 + wn * 64 + j * 8 + qid * 2;
            float2 bv = *(const float2*)(bias + col);
            int mA = mt * 128 + wm * 32 + mi * 16 + gid;
            int mB = mA + 8;
            float* dA; float* dB;
            if (MODE == 0) {
                dA = g_acc + (size_t)mA * H_SZ + col;
                dB = g_acc + (size_t)mB * H_SZ + col;
            } else {
                dA = dst_ext + ((size_t)(mA & 63) * T_STEPS + (mA >> 6)) * O_SZ + col;
                dB = dst_ext + ((size_t)(mB & 63) * T_STEPS + (mB >> 6)) * O_SZ + col;
            }
            *(float2*)dA = make_float2(acc[mi][j][0] + bv.x, acc[mi][j][1] + bv.y);
            *(float2*)dB = make_float2(acc[mi][j][2] + bv.x, acc[mi][j][3] + bv.y);
        }
    }
}

// ---------------------------------------------------------------------------
// Flat grid barrier (R5-proven). Used ONCE at end of rec for flag reset.
// ---------------------------------------------------------------------------
__device__ __forceinline__ void grid_barrier(int slot) {
    __syncthreads();
    if (threadIdx.x == 0) {
        volatile unsigned* fl = &g_flag[slot];
        unsigned prev = *fl;
        __threadfence();
        unsigned old = atomicAdd(&g_cnt[slot], 1u);
        if (old == NCTA - 1) {
            atomicExch(&g_cnt[slot], 0u);
            __threadfence();
            atomicAdd(&g_flag[slot], 1u);
        } else {
            while (*fl == prev) { }
        }
        __threadfence();
    }
    __syncthreads();
}

// ---------------------------------------------------------------------------
// Persistent recurrence, clustered + flag-pipelined.
// ct = blockIdx.x >> 3 (n-tile of 64 = "chunk ct"), kc = blockIdx.x & 7.
// Per step: wait the 16 sub-flags of chunks {2kc, 2kc+1} (producers of this
// CTA's h k-slice) -> stage h -> mma -> parts[t&1] -> cluster.sync ->
// in-cluster reduce+tanh+split -> publish own sub-flag. NO grid barrier.
// Replay safety: flags reset to 0 behind a final grid barrier.
// WAR on parts: double buffer + cluster.sync bounds mate skew to <1 step
// (a mate can't reach store(t+2) before all mates pass sync(t+1), which
// requires reduce(t) done).
// ---------------------------------------------------------------------------
#define R_WHI 0
#define R_WLO (64 * RPAD)
#define R_AHI (2 * 64 * RPAD)
#define R_ALO (3 * 64 * RPAD)
#define SMEM_REC_BYTES (4 * 64 * RPAD * 2)

__global__ __launch_bounds__(256) __cluster_dims__(KSPLIT, 1, 1)
void rec_mma(float* __restrict__ hid_out)
{
    extern __shared__ __nv_bfloat16 rs[];
    const int tid = threadIdx.x, wid = tid >> 5, lane = tid & 31;
    const int ct  = blockIdx.x >> 3;
    const int kc  = blockIdx.x & 7;
    const int wm  = wid >> 1, wn = wid & 1;

    // one-time Wh tile load: rows n = ct*64 .. +64, cols k = kc*128 .. +128
    {
        const size_t base = (size_t)(ct * 64) * H_SZ + kc * 128;
#pragma unroll
        for (int i = 0; i < 4; i++) {
            int ch = tid + i * 256;
            int r  = ch >> 4;
            int co = (ch & 15) * 8;
            *(uint4*)(rs + R_WHI + r * RPAD + co) =
                *(const uint4*)(g_WhThi + base + (size_t)r * H_SZ + co);
            *(uint4*)(rs + R_WLO + r * RPAD + co) =
                *(const uint4*)(g_WhTlo + base + (size_t)r * H_SZ + co);
        }
    }

    const u32 sbase = smem_u32(rs);
    const int a_row = lane & 15, a_kq = lane >> 4;
    const int b_nr = (lane >> 4) * 8 + (lane & 7), b_kq = (lane >> 3) & 1;
    const int gid = lane >> 2, qid = lane & 3;

    // reduce mapping: rows kc*8 + (tid>>5), cols ct*64 + (tid&31)*2
    const int red_row = kc * 8 + (tid >> 5);
    const size_t red_off = (size_t)red_row * H_SZ + ct * 64 + (tid & 31) * 2;

    // flag this thread polls (tid 0..7 -> chunk 2kc, tid 8..15 -> chunk 2kc+1)
    volatile u32* myflag = (tid < 16)
        ? &g_stepf[2 * kc + (tid >> 3)][tid & 7] : (volatile u32*)0;

#pragma unroll 1
    for (int t = 0; t < T_STEPS; t++) {
        const __nv_bfloat16* hhi = t ? (g_hsbhi + (size_t)(t - 1) * BH) : g_h0hi;
        const __nv_bfloat16* hlo = t ? (g_hsblo + (size_t)(t - 1) * BH) : g_h0lo;
        float* parts = g_parts[t & 1];

        // prefetch pre-activation for the reduce (barrier-independent)
        float2 aacc = *(const float2*)(g_acc + (size_t)t * BH + red_off);

        // wait for the two producer chunks of this CTA's h k-slice
        if (t > 0) {
            if (tid < 16) {
                while (*myflag < (u32)t) { }
                __threadfence();   // acquire
            }
            __syncthreads();
        }

        // load h slice: rows b = 0..63, cols k = kc*128 .. +128
#pragma unroll
        for (int i = 0; i < 4; i++) {
            int ch = tid + i * 256;
            int r  = ch >> 4;
            int co = (ch & 15) * 8;
            size_t off = (size_t)r * H_SZ + kc * 128 + co;
            *(uint4*)(rs + R_AHI + r * RPAD + co) = __ldcg((const uint4*)(hhi + off));
            *(uint4*)(rs + R_ALO + r * RPAD + co) = __ldcg((const uint4*)(hlo + off));
        }
        __syncthreads();

        float acc[4][4];
#pragma unroll
        for (int j = 0; j < 4; j++)
#pragma unroll
            for (int v = 0; v < 4; v++) acc[j][v] = 0.f;

#pragma unroll
        for (int ks = 0; ks < 8; ks++) {
            const int k0 = ks * 16;
            u32 ahi[4], alo[4], bhi[4][2], blo[4][2];
            {
                u32 off = (u32)((wm * 16 + a_row) * RPAD + k0 + a_kq * 8) * 2;
                ldmx4(ahi[0], ahi[1], ahi[2], ahi[3], sbase + R_AHI * 2 + off);
                ldmx4(alo[0], alo[1], alo[2], alo[3], sbase + R_ALO * 2 + off);
            }
#pragma unroll
            for (int ni = 0; ni < 2; ni++) {
                u32 off = (u32)((wn * 32 + ni * 16 + b_nr) * RPAD + k0 + b_kq * 8) * 2;
                ldmx4(bhi[2*ni][0], bhi[2*ni][1], bhi[2*ni+1][0], bhi[2*ni+1][1],
                      sbase + R_WHI * 2 + off);
                ldmx4(blo[2*ni][0], blo[2*ni][1], blo[2*ni+1][0], blo[2*ni+1][1],
                      sbase + R_WLO * 2 + off);
            }
#pragma unroll
            for (int j = 0; j < 4; j++) {
                mma16816(acc[j], ahi, bhi[j]);
                mma16816(acc[j], ahi, blo[j]);
                mma16816(acc[j], alo, bhi[j]);
            }
        }

        // partial store: rows wm*16+gid(+8), cols ct*64 + wn*32 + j*8 + qid*2
        {
            float* p0 = parts + (size_t)kc * BH
                      + (size_t)(wm * 16 + gid) * H_SZ + ct * 64 + wn * 32;
            float* p1 = p0 + 8 * H_SZ;
#pragma unroll
            for (int j = 0; j < 4; j++) {
                *(float2*)(p0 + j * 8 + qid * 2) = make_float2(acc[j][0], acc[j][1]);
                *(float2*)(p1 + j * 8 + qid * 2) = make_float2(acc[j][2], acc[j][3]);
            }
        }

        // cluster-local barrier: partials of this ct-tile visible to cluster
        __threadfence();
        asm volatile("barrier.cluster.arrive.aligned;" ::: "memory");
        asm volatile("barrier.cluster.wait.aligned;"   ::: "memory");

        // in-cluster reduce + tanh + bf16 hi/lo split (all 256 threads, 2 els)
        {
            float2 a = aacc;
#pragma unroll
            for (int p = 0; p < KSPLIT; p++) {
                float2 q = __ldcg((const float2*)(parts + (size_t)p * BH + red_off));
                a.x += q.x; a.y += q.y;
            }
            a.x = tanhf(a.x); a.y = tanhf(a.y);

            __nv_bfloat16 h0 = __float2bfloat16(a.x), h1 = __float2bfloat16(a.y);
            __nv_bfloat16 hh[2] = {h0, h1};
            __nv_bfloat16 ll[2] = {
                __float2bfloat16(a.x - __bfloat162float(h0)),
                __float2bfloat16(a.y - __bfloat162float(h1))};
            *(u32*)(g_hsbhi + (size_t)t * BH + red_off) = *(u32*)hh;
            *(u32*)(g_hsblo + (size_t)t * BH + red_off) = *(u32*)ll;

            if (hid_out && t == T_STEPS - 1)
                *(float2*)(hid_out + red_off) = a;
        }

        // publish: this CTA's rows of chunk ct for step t are written
        __threadfence();       // release (each thread's h writes)
        __syncthreads();       // all 256 threads' writes done
        if (tid == 0)
            *(volatile u32*)&g_stepf[ct][kc] = (u32)(t + 1);
    }

    // reset flags for graph replay (behind a full grid barrier)
    grid_barrier(0);
    if (blockIdx.x == 0 && tid < 128) {
        ((u32*)g_stepf)[tid] = 0;
    }
}

// ---------------------------------------------------------------------------
extern "C" void kernel_launch(void* const* d_in, const int* in_sizes, int n_in,
                              void* d_out, int out_size)
{
    const int*   input   = (const int*)  d_in[0];
    const float* hidden0 = (const float*)d_in[1];
    const float* emb     = (const float*)d_in[2];
    const float* Wi      = (const float*)d_in[3];
    const float* bi      = (const float*)d_in[4];
    const float* Wh      = (const float*)d_in[5];
    const float* bh      = (const float*)d_in[6];
    const float* Wo      = (const float*)d_in[7];
    const float* bo      = (const float*)d_in[8];
    float* out = (float*)d_out;

    float* hid_out = (out_size >= M_TOT * O_SZ + BH) ? out + (size_t)M_TOT * O_SZ
                                                     : (float*)0;

    cudaFuncSetAttribute(gemm_mma<0>, cudaFuncAttributeMaxDynamicSharedMemorySize, SMEM_GEMM_BYTES);
    cudaFuncSetAttribute(gemm_mma<1>, cudaFuncAttributeMaxDynamicSharedMemorySize, SMEM_GEMM_BYTES);
    cudaFuncSetAttribute(rec_mma, cudaFuncAttributeMaxDynamicSharedMemorySize, SMEM_REC_BYTES);

    prep_bias<<<4, 256>>>(bi, bh);
    prep_transpose<0><<<dim3(32, 32), 256>>>(Wi);
    prep_transpose<1><<<dim3(32, 32), 256>>>(Wo);
    prep_transpose<2><<<dim3(32, 32), 256>>>(Wh);
    prep_h0<<<64, 256>>>(hidden0);
    prep_gather<<<8192, 256>>>(input, emb);

    gemm_mma<0><<<dim3(8, 128), 256, SMEM_GEMM_BYTES>>>((const float*)0, (float*)0);
    rec_mma<<<NCTA, 256, SMEM_REC_BYTES>>>(hid_out);
    gemm_mma<1><<<dim3(8, 128), 256, SMEM_GEMM_BYTES>>>(bo, out);
}

// round 9
// speedup vs baseline: 1.1755x; 1.0328x over previous
#include <cuda_runtime.h>
#include <cuda_bf16.h>
#include <math.h>

#define T_STEPS 256
#define B_SZ    64
#define H_SZ    1024
#define O_SZ    1024
#define BH      (B_SZ * H_SZ)        // 65536
#define M_TOT   (T_STEPS * B_SZ)     // 16384
#define KSPLIT  8                    // recurrence k-split == cluster size
#define NCTA    128
#define PAD     40                   // smem row stride (bf16) for big gemm tiles
#define RPAD    136                  // smem row stride (bf16) for rec tiles

typedef unsigned long long u64;
typedef unsigned int u32;

__device__ __forceinline__ u32 smem_u32(const void* p) {
    u32 a; asm("{ .reg .u64 t; cvta.to.shared.u64 t, %1; cvt.u32.u64 %0, t; }"
               : "=r"(a) : "l"(p));
    return a;
}

// ---- cp.async helpers (sm_80 baseline) -------------------------------------
__device__ __forceinline__ void cp16(u32 dst, const void* src) {
    asm volatile("cp.async.cg.shared.global [%0], [%1], 16;"
                 :: "r"(dst), "l"(src));
}
#define CP_COMMIT() asm volatile("cp.async.commit_group;" ::: "memory")
#define CP_WAIT0()  asm volatile("cp.async.wait_group 0;" ::: "memory")

// ---- mma.sync helpers (plain PTX, validated on this build) -----------------
__device__ __forceinline__ void ldmx4(u32& r0, u32& r1, u32& r2, u32& r3, u32 a) {
    asm volatile("ldmatrix.sync.aligned.m8n8.x4.shared.b16 {%0,%1,%2,%3}, [%4];"
                 : "=r"(r0), "=r"(r1), "=r"(r2), "=r"(r3) : "r"(a));
}
__device__ __forceinline__ void mma16816(float* c, const u32* a, const u32* b) {
    asm volatile(
        "mma.sync.aligned.m16n8k16.row.col.f32.bf16.bf16.f32 "
        "{%0,%1,%2,%3}, {%4,%5,%6,%7}, {%8,%9}, {%0,%1,%2,%3};"
        : "+f"(c[0]), "+f"(c[1]), "+f"(c[2]), "+f"(c[3])
        : "r"(a[0]), "r"(a[1]), "r"(a[2]), "r"(a[3]), "r"(b[0]), "r"(b[1]));
}

// ---- scratch ---------------------------------------------------------------
__device__ float g_acc[(size_t)M_TOT * H_SZ];      // ix + bi + bh
__device__ __nv_bfloat16 g_A1hi[(size_t)M_TOT * H_SZ];
__device__ __nv_bfloat16 g_A1lo[(size_t)M_TOT * H_SZ];
__device__ __nv_bfloat16 g_hsbhi[(size_t)M_TOT * H_SZ];   // h states hi (bf16)
__device__ __nv_bfloat16 g_hsblo[(size_t)M_TOT * H_SZ];   // h states lo
__device__ __nv_bfloat16 g_h0hi[BH];
__device__ __nv_bfloat16 g_h0lo[BH];
__device__ __nv_bfloat16 g_WiThi[(size_t)H_SZ * H_SZ];    // [n][k]
__device__ __nv_bfloat16 g_WiTlo[(size_t)H_SZ * H_SZ];
__device__ __nv_bfloat16 g_WoThi[(size_t)H_SZ * O_SZ];
__device__ __nv_bfloat16 g_WoTlo[(size_t)H_SZ * O_SZ];
__device__ __nv_bfloat16 g_WhThi[(size_t)H_SZ * H_SZ];
__device__ __nv_bfloat16 g_WhTlo[(size_t)H_SZ * H_SZ];
__device__ float g_parts[2][(size_t)KSPLIT * BH];  // double-buffered by t&1
__device__ float g_bias1[H_SZ];
__device__ unsigned g_cnt[2];      // flat barrier counter (end-of-kernel only)
__device__ unsigned g_flag[2];     // monotonic release flag
__device__ u32 g_stepf[16][8];     // per-(chunk ct, sub kc) progress flags

// ---------------------------------------------------------------------------
// Prep kernels
// ---------------------------------------------------------------------------
__global__ void prep_bias(const float* __restrict__ bi, const float* __restrict__ bh) {
    int i = blockIdx.x * 256 + threadIdx.x;
    g_bias1[i] = bi[i] + bh[i];
}

template<int W>
__global__ void prep_transpose(const float* __restrict__ src) {
    __shared__ float ts[32][33];
    __nv_bfloat16* dhi = (W == 0) ? g_WiThi : (W == 1) ? g_WoThi : g_WhThi;
    __nv_bfloat16* dlo = (W == 0) ? g_WiTlo : (W == 1) ? g_WoTlo : g_WhTlo;
    int n0 = blockIdx.x * 32, k0 = blockIdx.y * 32;
    int tx = threadIdx.x & 31, ty = threadIdx.x >> 5;
#pragma unroll
    for (int i = 0; i < 4; i++)
        ts[ty + i * 8][tx] = src[(size_t)(k0 + ty + i * 8) * H_SZ + n0 + tx];
    __syncthreads();
#pragma unroll
    for (int i = 0; i < 4; i++) {
        int n = n0 + ty + i * 8;
        float v = ts[tx][ty + i * 8];
        __nv_bfloat16 h = __float2bfloat16(v);
        float r = v - __bfloat162float(h);
        dhi[(size_t)n * H_SZ + k0 + tx] = h;
        dlo[(size_t)n * H_SZ + k0 + tx] = __float2bfloat16(r);
    }
}

struct __align__(16) bf8 { __nv_bfloat16 v[8]; };

__global__ void prep_gather(const int* __restrict__ input, const float* __restrict__ emb) {
    size_t g = (size_t)blockIdx.x * 256 + threadIdx.x;
    size_t e = g * 8;
    int m = (int)(e >> 10), k = (int)(e & 1023);
    int t = m >> 6, b = m & 63;
    int row = input[b * T_STEPS + t];
    float4 v0 = *(const float4*)(emb + (size_t)row * H_SZ + k);
    float4 v1 = *(const float4*)(emb + (size_t)row * H_SZ + k + 4);
    float vv[8] = {v0.x, v0.y, v0.z, v0.w, v1.x, v1.y, v1.z, v1.w};
    bf8 hh, ll;
#pragma unroll
    for (int i = 0; i < 8; i++) {
        __nv_bfloat16 h = __float2bfloat16(vv[i]);
        hh.v[i] = h;
        ll.v[i] = __float2bfloat16(vv[i] - __bfloat162float(h));
    }
    *(bf8*)(g_A1hi + e) = hh;
    *(bf8*)(g_A1lo + e) = ll;
}

__global__ void prep_h0(const float* __restrict__ hidden0) {
    size_t e = ((size_t)blockIdx.x * 256 + threadIdx.x) * 4;
    float4 v = *(const float4*)(hidden0 + e);
    float vv[4] = {v.x, v.y, v.z, v.w};
    __nv_bfloat16 hh[4], ll[4];
#pragma unroll
    for (int i = 0; i < 4; i++) {
        hh[i] = __float2bfloat16(vv[i]);
        ll[i] = __float2bfloat16(vv[i] - __bfloat162float(hh[i]));
    }
    *(uint2*)(g_h0hi + e) = *(uint2*)hh;
    *(uint2*)(g_h0lo + e) = *(uint2*)ll;
}

// ---------------------------------------------------------------------------
// mma.sync big GEMM, cp.async pipelined: 128x128 CTA tile.
// ---------------------------------------------------------------------------
#define TILE_BF (128 * PAD)
#define SMEM_GEMM_BYTES (2 * 4 * TILE_BF * 2)

template<int MODE>
__global__ __launch_bounds__(256) void gemm_mma(const float* __restrict__ bias_ext,
                                                float* __restrict__ dst_ext)
{
    extern __shared__ __nv_bfloat16 sm[];
    const int tid = threadIdx.x, wid = tid >> 5, lane = tid & 31;
    const int nt = blockIdx.x, mt = blockIdx.y;
    const int wm = wid >> 1, wn = wid & 1;

    const __nv_bfloat16* Ahi = MODE ? g_hsbhi : g_A1hi;
    const __nv_bfloat16* Alo = MODE ? g_hsblo : g_A1lo;
    const __nv_bfloat16* Bhi = MODE ? g_WoThi : g_WiThi;
    const __nv_bfloat16* Blo = MODE ? g_WoTlo : g_WiTlo;
    const float* bias = MODE ? bias_ext : g_bias1;

    const __nv_bfloat16* srcT[4] = { Ahi + (size_t)mt * 128 * H_SZ,
                                     Alo + (size_t)mt * 128 * H_SZ,
                                     Bhi + (size_t)nt * 128 * H_SZ,
                                     Blo + (size_t)nt * 128 * H_SZ };

    const int r0 = tid >> 2, q0 = tid & 3;
    const int r1 = r0 + 64;

    const u32 sbase = smem_u32(sm);

    // ---- chunk 0 into buffer 0 via cp.async ----
#pragma unroll
    for (int t4 = 0; t4 < 4; t4++) {
        const __nv_bfloat16* s = srcT[t4];
        u32 d = sbase + (u32)(t4 * TILE_BF) * 2;
        cp16(d + (u32)(r0 * PAD + q0 * 8) * 2, s + (size_t)r0 * H_SZ + q0 * 8);
        cp16(d + (u32)(r1 * PAD + q0 * 8) * 2, s + (size_t)r1 * H_SZ + q0 * 8);
    }
    CP_COMMIT(); CP_WAIT0();
    __syncthreads();

    float acc[2][8][4];
#pragma unroll
    for (int mi = 0; mi < 2; mi++)
#pragma unroll
        for (int j = 0; j < 8; j++)
#pragma unroll
            for (int v = 0; v < 4; v++) acc[mi][j][v] = 0.f;

    const int a_row = lane & 15, a_kq = lane >> 4;
    const int b_nr = (lane >> 4) * 8 + (lane & 7), b_kq = (lane >> 3) & 1;

#pragma unroll 1
    for (int c = 0; c < 32; c++) {
        const int buf = c & 1;
        // issue async loads for next chunk into buf^1 (overlap with mma below)
        if (c < 31) {
            const int col0 = (c + 1) * 32;
#pragma unroll
            for (int t4 = 0; t4 < 4; t4++) {
                const __nv_bfloat16* s = srcT[t4] + col0;
                u32 d = sbase + (u32)(((buf ^ 1) * 4 + t4) * TILE_BF) * 2;
                cp16(d + (u32)(r0 * PAD + q0 * 8) * 2, s + (size_t)r0 * H_SZ + q0 * 8);
                cp16(d + (u32)(r1 * PAD + q0 * 8) * 2, s + (size_t)r1 * H_SZ + q0 * 8);
            }
            CP_COMMIT();
        }

        const u32 bA = sbase + (u32)(buf * 4) * TILE_BF * 2;
#pragma unroll
        for (int s = 0; s < 2; s++) {
            const int kc0 = s * 16;
            u32 ahi[2][4], alo[2][4], bhi[8][2], blo[8][2];
#pragma unroll
            for (int mi = 0; mi < 2; mi++) {
                u32 off = (u32)((wm * 32 + mi * 16 + a_row) * PAD + kc0 + a_kq * 8) * 2;
                ldmx4(ahi[mi][0], ahi[mi][1], ahi[mi][2], ahi[mi][3], bA + 0 * TILE_BF * 2 + off);
                ldmx4(alo[mi][0], alo[mi][1], alo[mi][2], alo[mi][3], bA + 1 * TILE_BF * 2 + off);
            }
#pragma unroll
            for (int ni = 0; ni < 4; ni++) {
                u32 off = (u32)((wn * 64 + ni * 16 + b_nr) * PAD + kc0 + b_kq * 8) * 2;
                ldmx4(bhi[2*ni][0], bhi[2*ni][1], bhi[2*ni+1][0], bhi[2*ni+1][1],
                      bA + 2 * TILE_BF * 2 + off);
                ldmx4(blo[2*ni][0], blo[2*ni][1], blo[2*ni+1][0], blo[2*ni+1][1],
                      bA + 3 * TILE_BF * 2 + off);
            }
#pragma unroll
            for (int mi = 0; mi < 2; mi++)
#pragma unroll
                for (int j = 0; j < 8; j++) {
                    mma16816(acc[mi][j], ahi[mi], bhi[j]);
                    mma16816(acc[mi][j], ahi[mi], blo[j]);
                    mma16816(acc[mi][j], alo[mi], bhi[j]);
                }
        }
        if (c < 31) CP_WAIT0();
        __syncthreads();
    }

    const int gid = lane >> 2, qid = lane & 3;
#pragma unroll
    for (int mi = 0; mi < 2; mi++) {
#pragma unroll
        for (int j = 0; j < 8; j++) {
            int col = nt * 128 + wn * 64 + j * 8 + qid * 2;
            float2 bv = *(const float2*)(bias + col);
            int mA = mt * 128 + wm * 32 + mi * 16 + gid;
            int mB = mA + 8;
            float* dA; float* dB;
            if (MODE == 0) {
                dA = g_acc + (size_t)mA * H_SZ + col;
                dB = g_acc + (size_t)mB * H_SZ + col;
            } else {
                dA = dst_ext + ((size_t)(mA & 63) * T_STEPS + (mA >> 6)) * O_SZ + col;
                dB = dst_ext + ((size_t)(mB & 63) * T_STEPS + (mB >> 6)) * O_SZ + col;
            }
            *(float2*)dA = make_float2(acc[mi][j][0] + bv.x, acc[mi][j][1] + bv.y);
            *(float2*)dB = make_float2(acc[mi][j][2] + bv.x, acc[mi][j][3] + bv.y);
        }
    }
}

// ---------------------------------------------------------------------------
// Flat grid barrier (R5-proven). Used ONCE at end of rec for flag reset.
// ---------------------------------------------------------------------------
__device__ __forceinline__ void grid_barrier(int slot) {
    __syncthreads();
    if (threadIdx.x == 0) {
        volatile unsigned* fl = &g_flag[slot];
        unsigned prev = *fl;
        __threadfence();
        unsigned old = atomicAdd(&g_cnt[slot], 1u);
        if (old == NCTA - 1) {
            atomicExch(&g_cnt[slot], 0u);
            __threadfence();
            atomicAdd(&g_flag[slot], 1u);
        } else {
            while (*fl == prev) { }
        }
        __threadfence();
    }
    __syncthreads();
}

// ---------------------------------------------------------------------------
// Persistent recurrence, clustered + flag-pipelined (R8-proven) with
// cp.async h staging.
// ---------------------------------------------------------------------------
#define R_WHI 0
#define R_WLO (64 * RPAD)
#define R_AHI (2 * 64 * RPAD)
#define R_ALO (3 * 64 * RPAD)
#define SMEM_REC_BYTES (4 * 64 * RPAD * 2)

__global__ __launch_bounds__(256) __cluster_dims__(KSPLIT, 1, 1)
void rec_mma(float* __restrict__ hid_out)
{
    extern __shared__ __nv_bfloat16 rs[];
    const int tid = threadIdx.x, wid = tid >> 5, lane = tid & 31;
    const int ct  = blockIdx.x >> 3;
    const int kc  = blockIdx.x & 7;
    const int wm  = wid >> 1, wn = wid & 1;

    // one-time Wh tile load: rows n = ct*64 .. +64, cols k = kc*128 .. +128
    {
        const size_t base = (size_t)(ct * 64) * H_SZ + kc * 128;
#pragma unroll
        for (int i = 0; i < 4; i++) {
            int ch = tid + i * 256;
            int r  = ch >> 4;
            int co = (ch & 15) * 8;
            *(uint4*)(rs + R_WHI + r * RPAD + co) =
                *(const uint4*)(g_WhThi + base + (size_t)r * H_SZ + co);
            *(uint4*)(rs + R_WLO + r * RPAD + co) =
                *(const uint4*)(g_WhTlo + base + (size_t)r * H_SZ + co);
        }
    }

    const u32 sbase = smem_u32(rs);
    const int a_row = lane & 15, a_kq = lane >> 4;
    const int b_nr = (lane >> 4) * 8 + (lane & 7), b_kq = (lane >> 3) & 1;
    const int gid = lane >> 2, qid = lane & 3;

    // reduce mapping: rows kc*8 + (tid>>5), cols ct*64 + (tid&31)*2
    const int red_row = kc * 8 + (tid >> 5);
    const size_t red_off = (size_t)red_row * H_SZ + ct * 64 + (tid & 31) * 2;

    // flag this thread polls (tid 0..7 -> chunk 2kc, tid 8..15 -> chunk 2kc+1)
    volatile u32* myflag = (tid < 16)
        ? &g_stepf[2 * kc + (tid >> 3)][tid & 7] : (volatile u32*)0;

#pragma unroll 1
    for (int t = 0; t < T_STEPS; t++) {
        const __nv_bfloat16* hhi = t ? (g_hsbhi + (size_t)(t - 1) * BH) : g_h0hi;
        const __nv_bfloat16* hlo = t ? (g_hsblo + (size_t)(t - 1) * BH) : g_h0lo;
        float* parts = g_parts[t & 1];

        // prefetch pre-activation for the reduce (barrier-independent)
        float2 aacc = *(const float2*)(g_acc + (size_t)t * BH + red_off);

        // wait for the two producer chunks of this CTA's h k-slice
        if (t > 0) {
            if (tid < 16) {
                while (*myflag < (u32)t) { }
                __threadfence();   // acquire
            }
            __syncthreads();
        }

        // stage h slice via cp.async (bypasses L1 -> coherent with peer STG)
#pragma unroll
        for (int i = 0; i < 4; i++) {
            int ch = tid + i * 256;
            int r  = ch >> 4;
            int co = (ch & 15) * 8;
            size_t off = (size_t)r * H_SZ + kc * 128 + co;
            cp16(sbase + (u32)(R_AHI + r * RPAD + co) * 2, hhi + off);
            cp16(sbase + (u32)(R_ALO + r * RPAD + co) * 2, hlo + off);
        }
        CP_COMMIT(); CP_WAIT0();
        __syncthreads();

        float acc[4][4];
#pragma unroll
        for (int j = 0; j < 4; j++)
#pragma unroll
            for (int v = 0; v < 4; v++) acc[j][v] = 0.f;

#pragma unroll
        for (int ks = 0; ks < 8; ks++) {
            const int k0 = ks * 16;
            u32 ahi[4], alo[4], bhi[4][2], blo[4][2];
            {
                u32 off = (u32)((wm * 16 + a_row) * RPAD + k0 + a_kq * 8) * 2;
                ldmx4(ahi[0], ahi[1], ahi[2], ahi[3], sbase + R_AHI * 2 + off);
                ldmx4(alo[0], alo[1], alo[2], alo[3], sbase + R_ALO * 2 + off);
            }
#pragma unroll
            for (int ni = 0; ni < 2; ni++) {
                u32 off = (u32)((wn * 32 + ni * 16 + b_nr) * RPAD + k0 + b_kq * 8) * 2;
                ldmx4(bhi[2*ni][0], bhi[2*ni][1], bhi[2*ni+1][0], bhi[2*ni+1][1],
                      sbase + R_WHI * 2 + off);
                ldmx4(blo[2*ni][0], blo[2*ni][1], blo[2*ni+1][0], blo[2*ni+1][1],
                      sbase + R_WLO * 2 + off);
            }
#pragma unroll
            for (int j = 0; j < 4; j++) {
                mma16816(acc[j], ahi, bhi[j]);
                mma16816(acc[j], ahi, blo[j]);
                mma16816(acc[j], alo, bhi[j]);
            }
        }

        // partial store: rows wm*16+gid(+8), cols ct*64 + wn*32 + j*8 + qid*2
        {
            float* p0 = parts + (size_t)kc * BH
                      + (size_t)(wm * 16 + gid) * H_SZ + ct * 64 + wn * 32;
            float* p1 = p0 + 8 * H_SZ;
#pragma unroll
            for (int j = 0; j < 4; j++) {
                *(float2*)(p0 + j * 8 + qid * 2) = make_float2(acc[j][0], acc[j][1]);
                *(float2*)(p1 + j * 8 + qid * 2) = make_float2(acc[j][2], acc[j][3]);
            }
        }

        // cluster-local barrier: partials of this ct-tile visible to cluster
        __threadfence();
        asm volatile("barrier.cluster.arrive.aligned;" ::: "memory");
        asm volatile("barrier.cluster.wait.aligned;"   ::: "memory");

        // in-cluster reduce + tanh + bf16 hi/lo split (all 256 threads, 2 els)
        {
            float2 a = aacc;
#pragma unroll
            for (int p = 0; p < KSPLIT; p++) {
                float2 q = __ldcg((const float2*)(parts + (size_t)p * BH + red_off));
                a.x += q.x; a.y += q.y;
            }
            a.x = tanhf(a.x); a.y = tanhf(a.y);

            __nv_bfloat16 h0 = __float2bfloat16(a.x), h1 = __float2bfloat16(a.y);
            __nv_bfloat16 hh[2] = {h0, h1};
            __nv_bfloat16 ll[2] = {
                __float2bfloat16(a.x - __bfloat162float(h0)),
                __float2bfloat16(a.y - __bfloat162float(h1))};
            *(u32*)(g_hsbhi + (size_t)t * BH + red_off) = *(u32*)hh;
            *(u32*)(g_hsblo + (size_t)t * BH + red_off) = *(u32*)ll;

            if (hid_out && t == T_STEPS - 1)
                *(float2*)(hid_out + red_off) = a;
        }

        // publish: this CTA's rows of chunk ct for step t are written
        __threadfence();       // release (each thread's h writes)
        __syncthreads();       // all 256 threads' writes done
        if (tid == 0)
            *(volatile u32*)&g_stepf[ct][kc] = (u32)(t + 1);
    }

    // reset flags for graph replay (behind a full grid barrier)
    grid_barrier(0);
    if (blockIdx.x == 0 && tid < 128) {
        ((u32*)g_stepf)[tid] = 0;
    }
}

// ---------------------------------------------------------------------------
extern "C" void kernel_launch(void* const* d_in, const int* in_sizes, int n_in,
                              void* d_out, int out_size)
{
    const int*   input   = (const int*)  d_in[0];
    const float* hidden0 = (const float*)d_in[1];
    const float* emb     = (const float*)d_in[2];
    const float* Wi      = (const float*)d_in[3];
    const float* bi      = (const float*)d_in[4];
    const float* Wh      = (const float*)d_in[5];
    const float* bh      = (const float*)d_in[6];
    const float* Wo      = (const float*)d_in[7];
    const float* bo      = (const float*)d_in[8];
    float* out = (float*)d_out;

    float* hid_out = (out_size >= M_TOT * O_SZ + BH) ? out + (size_t)M_TOT * O_SZ
                                                     : (float*)0;

    cudaFuncSetAttribute(gemm_mma<0>, cudaFuncAttributeMaxDynamicSharedMemorySize, SMEM_GEMM_BYTES);
    cudaFuncSetAttribute(gemm_mma<1>, cudaFuncAttributeMaxDynamicSharedMemorySize, SMEM_GEMM_BYTES);
    cudaFuncSetAttribute(rec_mma, cudaFuncAttributeMaxDynamicSharedMemorySize, SMEM_REC_BYTES);

    prep_bias<<<4, 256>>>(bi, bh);
    prep_transpose<0><<<dim3(32, 32), 256>>>(Wi);
    prep_transpose<1><<<dim3(32, 32), 256>>>(Wo);
    prep_transpose<2><<<dim3(32, 32), 256>>>(Wh);
    prep_h0<<<64, 256>>>(hidden0);
    prep_gather<<<8192, 256>>>(input, emb);

    gemm_mma<0><<<dim3(8, 128), 256, SMEM_GEMM_BYTES>>>((const float*)0, (float*)0);
    rec_mma<<<NCTA, 256, SMEM_REC_BYTES>>>(hid_out);
    gemm_mma<1><<<dim3(8, 128), 256, SMEM_GEMM_BYTES>>>(bo, out);
}

// round 10
// speedup vs baseline: 1.2567x; 1.0691x over previous
#include <cuda_runtime.h>
#include <cuda_bf16.h>
#include <cuda_fp16.h>
#include <math.h>

#define T_STEPS 256
#define B_SZ    64
#define H_SZ    1024
#define O_SZ    1024
#define BH      (B_SZ * H_SZ)        // 65536
#define M_TOT   (T_STEPS * B_SZ)     // 16384
#define KSPLIT  8                    // recurrence k-split == cluster size
#define NCTA    128
#define PAD     40                   // smem row stride (16-bit elems), big gemms
#define RPAD    136                  // smem row stride (16-bit elems), rec tiles

typedef unsigned long long u64;
typedef unsigned int u32;

__device__ __forceinline__ u32 smem_u32(const void* p) {
    u32 a; asm("{ .reg .u64 t; cvta.to.shared.u64 t, %1; cvt.u32.u64 %0, t; }"
               : "=r"(a) : "l"(p));
    return a;
}

// ---- cp.async helpers ------------------------------------------------------
__device__ __forceinline__ void cp16(u32 dst, const void* src) {
    asm volatile("cp.async.cg.shared.global [%0], [%1], 16;"
                 :: "r"(dst), "l"(src));
}
#define CP_COMMIT() asm volatile("cp.async.commit_group;" ::: "memory")
#define CP_WAIT0()  asm volatile("cp.async.wait_group 0;" ::: "memory")

// ---- mma.sync helpers ------------------------------------------------------
__device__ __forceinline__ void ldmx4(u32& r0, u32& r1, u32& r2, u32& r3, u32 a) {
    asm volatile("ldmatrix.sync.aligned.m8n8.x4.shared.b16 {%0,%1,%2,%3}, [%4];"
                 : "=r"(r0), "=r"(r1), "=r"(r2), "=r"(r3) : "r"(a));
}
__device__ __forceinline__ void mma_bf(float* c, const u32* a, const u32* b) {
    asm volatile(
        "mma.sync.aligned.m16n8k16.row.col.f32.bf16.bf16.f32 "
        "{%0,%1,%2,%3}, {%4,%5,%6,%7}, {%8,%9}, {%0,%1,%2,%3};"
        : "+f"(c[0]), "+f"(c[1]), "+f"(c[2]), "+f"(c[3])
        : "r"(a[0]), "r"(a[1]), "r"(a[2]), "r"(a[3]), "r"(b[0]), "r"(b[1]));
}
__device__ __forceinline__ void mma_f16(float* c, const u32* a, const u32* b) {
    asm volatile(
        "mma.sync.aligned.m16n8k16.row.col.f32.f16.f16.f32 "
        "{%0,%1,%2,%3}, {%4,%5,%6,%7}, {%8,%9}, {%0,%1,%2,%3};"
        : "+f"(c[0]), "+f"(c[1]), "+f"(c[2]), "+f"(c[3])
        : "r"(a[0]), "r"(a[1]), "r"(a[2]), "r"(a[3]), "r"(b[0]), "r"(b[1]));
}

// ---- scratch ---------------------------------------------------------------
__device__ float g_acc[(size_t)M_TOT * H_SZ];      // ix + bi + bh (fp32)
__device__ __nv_bfloat16 g_A1hi[(size_t)M_TOT * H_SZ];   // K1 A operand (bf16 3-term)
__device__ __nv_bfloat16 g_A1lo[(size_t)M_TOT * H_SZ];
__device__ __nv_bfloat16 g_WiThi[(size_t)H_SZ * H_SZ];   // [n][k] bf16
__device__ __nv_bfloat16 g_WiTlo[(size_t)H_SZ * H_SZ];
__device__ __half g_hsf[(size_t)M_TOT * H_SZ];     // h states, single fp16
__device__ __half g_h0f[BH];
__device__ __half g_WoThf[(size_t)H_SZ * O_SZ];    // fp16 hi/lo [n][k]
__device__ __half g_WoTlf[(size_t)H_SZ * O_SZ];
__device__ __half g_WhThf[(size_t)H_SZ * H_SZ];
__device__ __half g_WhTlf[(size_t)H_SZ * H_SZ];
__device__ float g_parts[2][(size_t)KSPLIT * BH];  // double-buffered by t&1
__device__ float g_bias1[H_SZ];
__device__ unsigned g_cnt[2];
__device__ unsigned g_flag[2];
__device__ u32 g_stepf[16][8];

// ---------------------------------------------------------------------------
// Prep kernels
// ---------------------------------------------------------------------------
__global__ void prep_bias(const float* __restrict__ bi, const float* __restrict__ bh) {
    int i = blockIdx.x * 256 + threadIdx.x;
    g_bias1[i] = bi[i] + bh[i];
}

// W=0: Wi -> bf16 hi/lo (3-term path)
__global__ void prep_transpose_bf(const float* __restrict__ src) {
    __shared__ float ts[32][33];
    int n0 = blockIdx.x * 32, k0 = blockIdx.y * 32;
    int tx = threadIdx.x & 31, ty = threadIdx.x >> 5;
#pragma unroll
    for (int i = 0; i < 4; i++)
        ts[ty + i * 8][tx] = src[(size_t)(k0 + ty + i * 8) * H_SZ + n0 + tx];
    __syncthreads();
#pragma unroll
    for (int i = 0; i < 4; i++) {
        int n = n0 + ty + i * 8;
        float v = ts[tx][ty + i * 8];
        __nv_bfloat16 h = __float2bfloat16(v);
        float r = v - __bfloat162float(h);
        g_WiThi[(size_t)n * H_SZ + k0 + tx] = h;
        g_WiTlo[(size_t)n * H_SZ + k0 + tx] = __float2bfloat16(r);
    }
}

// W=1: Wo, W=2: Wh -> fp16 hi/lo (2-term path)
template<int W>
__global__ void prep_transpose_f16(const float* __restrict__ src) {
    __shared__ float ts[32][33];
    __half* dhi = (W == 1) ? g_WoThf : g_WhThf;
    __half* dlo = (W == 1) ? g_WoTlf : g_WhTlf;
    int n0 = blockIdx.x * 32, k0 = blockIdx.y * 32;
    int tx = threadIdx.x & 31, ty = threadIdx.x >> 5;
#pragma unroll
    for (int i = 0; i < 4; i++)
        ts[ty + i * 8][tx] = src[(size_t)(k0 + ty + i * 8) * H_SZ + n0 + tx];
    __syncthreads();
#pragma unroll
    for (int i = 0; i < 4; i++) {
        int n = n0 + ty + i * 8;
        float v = ts[tx][ty + i * 8];
        __half h = __float2half_rn(v);
        float r = v - __half2float(h);
        dhi[(size_t)n * H_SZ + k0 + tx] = h;
        dlo[(size_t)n * H_SZ + k0 + tx] = __float2half_rn(r);
    }
}

struct __align__(16) bf8 { __nv_bfloat16 v[8]; };

__global__ void prep_gather(const int* __restrict__ input, const float* __restrict__ emb) {
    size_t g = (size_t)blockIdx.x * 256 + threadIdx.x;
    size_t e = g * 8;
    int m = (int)(e >> 10), k = (int)(e & 1023);
    int t = m >> 6, b = m & 63;
    int row = input[b * T_STEPS + t];
    float4 v0 = *(const float4*)(emb + (size_t)row * H_SZ + k);
    float4 v1 = *(const float4*)(emb + (size_t)row * H_SZ + k + 4);
    float vv[8] = {v0.x, v0.y, v0.z, v0.w, v1.x, v1.y, v1.z, v1.w};
    bf8 hh, ll;
#pragma unroll
    for (int i = 0; i < 8; i++) {
        __nv_bfloat16 h = __float2bfloat16(vv[i]);
        hh.v[i] = h;
        ll.v[i] = __float2bfloat16(vv[i] - __bfloat162float(h));
    }
    *(bf8*)(g_A1hi + e) = hh;
    *(bf8*)(g_A1lo + e) = ll;
}

__global__ void prep_h0(const float* __restrict__ hidden0) {
    size_t e = ((size_t)blockIdx.x * 256 + threadIdx.x) * 4;
    float4 v = *(const float4*)(hidden0 + e);
    __half hh[4] = {__float2half_rn(v.x), __float2half_rn(v.y),
                    __float2half_rn(v.z), __float2half_rn(v.w)};
    *(uint2*)(g_h0f + e) = *(uint2*)hh;
}

// ---------------------------------------------------------------------------
// K1: bf16 3-term mma GEMM (proven R9 structure), 128x128 CTA tile.
// ---------------------------------------------------------------------------
#define TILE_BF (128 * PAD)
#define SMEM_G0 (2 * 4 * TILE_BF * 2)

__global__ __launch_bounds__(256) void gemm_ix(void)
{
    extern __shared__ __nv_bfloat16 sm[];
    const int tid = threadIdx.x, wid = tid >> 5, lane = tid & 31;
    const int nt = blockIdx.x, mt = blockIdx.y;
    const int wm = wid >> 1, wn = wid & 1;

    const __nv_bfloat16* srcT[4] = { g_A1hi + (size_t)mt * 128 * H_SZ,
                                     g_A1lo + (size_t)mt * 128 * H_SZ,
                                     g_WiThi + (size_t)nt * 128 * H_SZ,
                                     g_WiTlo + (size_t)nt * 128 * H_SZ };

    const int r0 = tid >> 2, q0 = tid & 3;
    const int r1 = r0 + 64;
    const u32 sbase = smem_u32(sm);

#pragma unroll
    for (int t4 = 0; t4 < 4; t4++) {
        const __nv_bfloat16* s = srcT[t4];
        u32 d = sbase + (u32)(t4 * TILE_BF) * 2;
        cp16(d + (u32)(r0 * PAD + q0 * 8) * 2, s + (size_t)r0 * H_SZ + q0 * 8);
        cp16(d + (u32)(r1 * PAD + q0 * 8) * 2, s + (size_t)r1 * H_SZ + q0 * 8);
    }
    CP_COMMIT(); CP_WAIT0();
    __syncthreads();

    float acc[2][8][4];
#pragma unroll
    for (int mi = 0; mi < 2; mi++)
#pragma unroll
        for (int j = 0; j < 8; j++)
#pragma unroll
            for (int v = 0; v < 4; v++) acc[mi][j][v] = 0.f;

    const int a_row = lane & 15, a_kq = lane >> 4;
    const int b_nr = (lane >> 4) * 8 + (lane & 7), b_kq = (lane >> 3) & 1;

#pragma unroll 1
    for (int c = 0; c < 32; c++) {
        const int buf = c & 1;
        if (c < 31) {
            const int col0 = (c + 1) * 32;
#pragma unroll
            for (int t4 = 0; t4 < 4; t4++) {
                const __nv_bfloat16* s = srcT[t4] + col0;
                u32 d = sbase + (u32)(((buf ^ 1) * 4 + t4) * TILE_BF) * 2;
                cp16(d + (u32)(r0 * PAD + q0 * 8) * 2, s + (size_t)r0 * H_SZ + q0 * 8);
                cp16(d + (u32)(r1 * PAD + q0 * 8) * 2, s + (size_t)r1 * H_SZ + q0 * 8);
            }
            CP_COMMIT();
        }

        const u32 bA = sbase + (u32)(buf * 4) * TILE_BF * 2;
#pragma unroll
        for (int s = 0; s < 2; s++) {
            const int kc0 = s * 16;
            u32 ahi[2][4], alo[2][4], bhi[8][2], blo[8][2];
#pragma unroll
            for (int mi = 0; mi < 2; mi++) {
                u32 off = (u32)((wm * 32 + mi * 16 + a_row) * PAD + kc0 + a_kq * 8) * 2;
                ldmx4(ahi[mi][0], ahi[mi][1], ahi[mi][2], ahi[mi][3], bA + 0 * TILE_BF * 2 + off);
                ldmx4(alo[mi][0], alo[mi][1], alo[mi][2], alo[mi][3], bA + 1 * TILE_BF * 2 + off);
            }
#pragma unroll
            for (int ni = 0; ni < 4; ni++) {
                u32 off = (u32)((wn * 64 + ni * 16 + b_nr) * PAD + kc0 + b_kq * 8) * 2;
                ldmx4(bhi[2*ni][0], bhi[2*ni][1], bhi[2*ni+1][0], bhi[2*ni+1][1],
                      bA + 2 * TILE_BF * 2 + off);
                ldmx4(blo[2*ni][0], blo[2*ni][1], blo[2*ni+1][0], blo[2*ni+1][1],
                      bA + 3 * TILE_BF * 2 + off);
            }
#pragma unroll
            for (int mi = 0; mi < 2; mi++)
#pragma unroll
                for (int j = 0; j < 8; j++) {
                    mma_bf(acc[mi][j], ahi[mi], bhi[j]);
                    mma_bf(acc[mi][j], ahi[mi], blo[j]);
                    mma_bf(acc[mi][j], alo[mi], bhi[j]);
                }
        }
        if (c < 31) CP_WAIT0();
        __syncthreads();
    }

    const int gid = lane >> 2, qid = lane & 3;
#pragma unroll
    for (int mi = 0; mi < 2; mi++) {
#pragma unroll
        for (int j = 0; j < 8; j++) {
            int col = nt * 128 + wn * 64 + j * 8 + qid * 2;
            float2 bv = *(const float2*)(g_bias1 + col);
            int mA = mt * 128 + wm * 32 + mi * 16 + gid;
            int mB = mA + 8;
            float* dA = g_acc + (size_t)mA * H_SZ + col;
            float* dB = g_acc + (size_t)mB * H_SZ + col;
            *(float2*)dA = make_float2(acc[mi][j][0] + bv.x, acc[mi][j][1] + bv.y);
            *(float2*)dB = make_float2(acc[mi][j][2] + bv.x, acc[mi][j][3] + bv.y);
        }
    }
}

// ---------------------------------------------------------------------------
// K3: fp16 2-term mma GEMM. A = hs (single fp16), B = Wo hi/lo fp16.
// ---------------------------------------------------------------------------
#define SMEM_G1 (2 * 3 * TILE_BF * 2)

__global__ __launch_bounds__(256) void gemm_out2(const float* __restrict__ bo,
                                                 float* __restrict__ out)
{
    extern __shared__ __half smh[];
    const int tid = threadIdx.x, wid = tid >> 5, lane = tid & 31;
    const int nt = blockIdx.x, mt = blockIdx.y;
    const int wm = wid >> 1, wn = wid & 1;

    const __half* srcT[3] = { g_hsf   + (size_t)mt * 128 * H_SZ,
                              g_WoThf + (size_t)nt * 128 * H_SZ,
                              g_WoTlf + (size_t)nt * 128 * H_SZ };

    const int r0 = tid >> 2, q0 = tid & 3;
    const int r1 = r0 + 64;
    const u32 sbase = smem_u32(smh);

#pragma unroll
    for (int t4 = 0; t4 < 3; t4++) {
        const __half* s = srcT[t4];
        u32 d = sbase + (u32)(t4 * TILE_BF) * 2;
        cp16(d + (u32)(r0 * PAD + q0 * 8) * 2, s + (size_t)r0 * H_SZ + q0 * 8);
        cp16(d + (u32)(r1 * PAD + q0 * 8) * 2, s + (size_t)r1 * H_SZ + q0 * 8);
    }
    CP_COMMIT(); CP_WAIT0();
    __syncthreads();

    float acc[2][8][4];
#pragma unroll
    for (int mi = 0; mi < 2; mi++)
#pragma unroll
        for (int j = 0; j < 8; j++)
#pragma unroll
            for (int v = 0; v < 4; v++) acc[mi][j][v] = 0.f;

    const int a_row = lane & 15, a_kq = lane >> 4;
    const int b_nr = (lane >> 4) * 8 + (lane & 7), b_kq = (lane >> 3) & 1;

#pragma unroll 1
    for (int c = 0; c < 32; c++) {
        const int buf = c & 1;
        if (c < 31) {
            const int col0 = (c + 1) * 32;
#pragma unroll
            for (int t4 = 0; t4 < 3; t4++) {
                const __half* s = srcT[t4] + col0;
                u32 d = sbase + (u32)(((buf ^ 1) * 3 + t4) * TILE_BF) * 2;
                cp16(d + (u32)(r0 * PAD + q0 * 8) * 2, s + (size_t)r0 * H_SZ + q0 * 8);
                cp16(d + (u32)(r1 * PAD + q0 * 8) * 2, s + (size_t)r1 * H_SZ + q0 * 8);
            }
            CP_COMMIT();
        }

        const u32 bA = sbase + (u32)(buf * 3) * TILE_BF * 2;
#pragma unroll
        for (int s = 0; s < 2; s++) {
            const int kc0 = s * 16;
            u32 a[2][4], bhi[8][2], blo[8][2];
#pragma unroll
            for (int mi = 0; mi < 2; mi++) {
                u32 off = (u32)((wm * 32 + mi * 16 + a_row) * PAD + kc0 + a_kq * 8) * 2;
                ldmx4(a[mi][0], a[mi][1], a[mi][2], a[mi][3], bA + 0 * TILE_BF * 2 + off);
            }
#pragma unroll
            for (int ni = 0; ni < 4; ni++) {
                u32 off = (u32)((wn * 64 + ni * 16 + b_nr) * PAD + kc0 + b_kq * 8) * 2;
                ldmx4(bhi[2*ni][0], bhi[2*ni][1], bhi[2*ni+1][0], bhi[2*ni+1][1],
                      bA + 1 * TILE_BF * 2 + off);
                ldmx4(blo[2*ni][0], blo[2*ni][1], blo[2*ni+1][0], blo[2*ni+1][1],
                      bA + 2 * TILE_BF * 2 + off);
            }
#pragma unroll
            for (int mi = 0; mi < 2; mi++)
#pragma unroll
                for (int j = 0; j < 8; j++) {
                    mma_f16(acc[mi][j], a[mi], bhi[j]);
                    mma_f16(acc[mi][j], a[mi], blo[j]);
                }
        }
        if (c < 31) CP_WAIT0();
        __syncthreads();
    }

    const int gid = lane >> 2, qid = lane & 3;
#pragma unroll
    for (int mi = 0; mi < 2; mi++) {
#pragma unroll
        for (int j = 0; j < 8; j++) {
            int col = nt * 128 + wn * 64 + j * 8 + qid * 2;
            float2 bv = *(const float2*)(bo + col);
            int mA = mt * 128 + wm * 32 + mi * 16 + gid;
            int mB = mA + 8;
            float* dA = out + ((size_t)(mA & 63) * T_STEPS + (mA >> 6)) * O_SZ + col;
            float* dB = out + ((size_t)(mB & 63) * T_STEPS + (mB >> 6)) * O_SZ + col;
            *(float2*)dA = make_float2(acc[mi][j][0] + bv.x, acc[mi][j][1] + bv.y);
            *(float2*)dB = make_float2(acc[mi][j][2] + bv.x, acc[mi][j][3] + bv.y);
        }
    }
}

// ---------------------------------------------------------------------------
// Flat grid barrier (proven). Used ONCE at end of rec for flag reset.
// ---------------------------------------------------------------------------
__device__ __forceinline__ void grid_barrier(int slot) {
    __syncthreads();
    if (threadIdx.x == 0) {
        volatile unsigned* fl = &g_flag[slot];
        unsigned prev = *fl;
        __threadfence();
        unsigned old = atomicAdd(&g_cnt[slot], 1u);
        if (old == NCTA - 1) {
            atomicExch(&g_cnt[slot], 0u);
            __threadfence();
            atomicAdd(&g_flag[slot], 1u);
        } else {
            while (*fl == prev) { }
        }
        __threadfence();
    }
    __syncthreads();
}

// ---------------------------------------------------------------------------
// Persistent recurrence, clustered + flag-pipelined (proven R9 structure),
// now fp16 2-term: A = h single fp16, B = Wh hi/lo fp16.
// ---------------------------------------------------------------------------
#define R_WHI 0
#define R_WLO (64 * RPAD)
#define R_A   (2 * 64 * RPAD)
#define SMEM_REC_BYTES (3 * 64 * RPAD * 2)

__global__ __launch_bounds__(256) __cluster_dims__(KSPLIT, 1, 1)
void rec_mma(float* __restrict__ hid_out)
{
    extern __shared__ __half rsh[];
    const int tid = threadIdx.x, wid = tid >> 5, lane = tid & 31;
    const int ct  = blockIdx.x >> 3;
    const int kc  = blockIdx.x & 7;
    const int wm  = wid >> 1, wn = wid & 1;

    // one-time Wh tile load: rows n = ct*64 .. +64, cols k = kc*128 .. +128
    {
        const size_t base = (size_t)(ct * 64) * H_SZ + kc * 128;
#pragma unroll
        for (int i = 0; i < 4; i++) {
            int ch = tid + i * 256;
            int r  = ch >> 4;
            int co = (ch & 15) * 8;
            *(uint4*)(rsh + R_WHI + r * RPAD + co) =
                *(const uint4*)(g_WhThf + base + (size_t)r * H_SZ + co);
            *(uint4*)(rsh + R_WLO + r * RPAD + co) =
                *(const uint4*)(g_WhTlf + base + (size_t)r * H_SZ + co);
        }
    }

    const u32 sbase = smem_u32(rsh);
    const int a_row = lane & 15, a_kq = lane >> 4;
    const int b_nr = (lane >> 4) * 8 + (lane & 7), b_kq = (lane >> 3) & 1;
    const int gid = lane >> 2, qid = lane & 3;

    // reduce mapping: rows kc*8 + (tid>>5), cols ct*64 + (tid&31)*2
    const int red_row = kc * 8 + (tid >> 5);
    const size_t red_off = (size_t)red_row * H_SZ + ct * 64 + (tid & 31) * 2;

    volatile u32* myflag = (tid < 16)
        ? &g_stepf[2 * kc + (tid >> 3)][tid & 7] : (volatile u32*)0;

#pragma unroll 1
    for (int t = 0; t < T_STEPS; t++) {
        const __half* hsrc = t ? (g_hsf + (size_t)(t - 1) * BH) : g_h0f;
        float* parts = g_parts[t & 1];

        float2 aacc = *(const float2*)(g_acc + (size_t)t * BH + red_off);

        if (t > 0) {
            if (tid < 16) {
                while (*myflag < (u32)t) { }
                __threadfence();
            }
            __syncthreads();
        }

        // stage h slice (64 x 128 fp16 = 16KB) via cp.async
#pragma unroll
        for (int i = 0; i < 4; i++) {
            int ch = tid + i * 256;
            int r  = ch >> 4;
            int co = (ch & 15) * 8;
            cp16(sbase + (u32)(R_A + r * RPAD + co) * 2,
                 hsrc + (size_t)r * H_SZ + kc * 128 + co);
        }
        CP_COMMIT(); CP_WAIT0();
        __syncthreads();

        float acc[4][4];
#pragma unroll
        for (int j = 0; j < 4; j++)
#pragma unroll
            for (int v = 0; v < 4; v++) acc[j][v] = 0.f;

#pragma unroll
        for (int ks = 0; ks < 8; ks++) {
            const int k0 = ks * 16;
            u32 a[4], bhi[4][2], blo[4][2];
            {
                u32 off = (u32)((wm * 16 + a_row) * RPAD + k0 + a_kq * 8) * 2;
                ldmx4(a[0], a[1], a[2], a[3], sbase + R_A * 2 + off);
            }
#pragma unroll
            for (int ni = 0; ni < 2; ni++) {
                u32 off = (u32)((wn * 32 + ni * 16 + b_nr) * RPAD + k0 + b_kq * 8) * 2;
                ldmx4(bhi[2*ni][0], bhi[2*ni][1], bhi[2*ni+1][0], bhi[2*ni+1][1],
                      sbase + R_WHI * 2 + off);
                ldmx4(blo[2*ni][0], blo[2*ni][1], blo[2*ni+1][0], blo[2*ni+1][1],
                      sbase + R_WLO * 2 + off);
            }
#pragma unroll
            for (int j = 0; j < 4; j++) {
                mma_f16(acc[j], a, bhi[j]);
                mma_f16(acc[j], a, blo[j]);
            }
        }

        // partial store
        {
            float* p0 = parts + (size_t)kc * BH
                      + (size_t)(wm * 16 + gid) * H_SZ + ct * 64 + wn * 32;
            float* p1 = p0 + 8 * H_SZ;
#pragma unroll
            for (int j = 0; j < 4; j++) {
                *(float2*)(p0 + j * 8 + qid * 2) = make_float2(acc[j][0], acc[j][1]);
                *(float2*)(p1 + j * 8 + qid * 2) = make_float2(acc[j][2], acc[j][3]);
            }
        }

        __threadfence();
        asm volatile("barrier.cluster.arrive.aligned;" ::: "memory");
        asm volatile("barrier.cluster.wait.aligned;"   ::: "memory");

        // in-cluster reduce + tanh + fp16 store
        {
            float2 a2 = aacc;
#pragma unroll
            for (int p = 0; p < KSPLIT; p++) {
                float2 q = __ldcg((const float2*)(parts + (size_t)p * BH + red_off));
                a2.x += q.x; a2.y += q.y;
            }
            a2.x = tanhf(a2.x); a2.y = tanhf(a2.y);

            __half h0 = __float2half_rn(a2.x), h1 = __float2half_rn(a2.y);
            u32 packed = (u32)__half_as_ushort(h0) | ((u32)__half_as_ushort(h1) << 16);
            *(u32*)(g_hsf + (size_t)t * BH + red_off) = packed;

            if (hid_out && t == T_STEPS - 1)
                *(float2*)(hid_out + red_off) = a2;
        }

        __threadfence();
        __syncthreads();
        if (tid == 0)
            *(volatile u32*)&g_stepf[ct][kc] = (u32)(t + 1);
    }

    grid_barrier(0);
    if (blockIdx.x == 0 && tid < 128) {
        ((u32*)g_stepf)[tid] = 0;
    }
}

// ---------------------------------------------------------------------------
extern "C" void kernel_launch(void* const* d_in, const int* in_sizes, int n_in,
                              void* d_out, int out_size)
{
    const int*   input   = (const int*)  d_in[0];
    const float* hidden0 = (const float*)d_in[1];
    const float* emb     = (const float*)d_in[2];
    const float* Wi      = (const float*)d_in[3];
    const float* bi      = (const float*)d_in[4];
    const float* Wh      = (const float*)d_in[5];
    const float* bh      = (const float*)d_in[6];
    const float* Wo      = (const float*)d_in[7];
    const float* bo      = (const float*)d_in[8];
    float* out = (float*)d_out;

    float* hid_out = (out_size >= M_TOT * O_SZ + BH) ? out + (size_t)M_TOT * O_SZ
                                                     : (float*)0;

    cudaFuncSetAttribute(gemm_ix,  cudaFuncAttributeMaxDynamicSharedMemorySize, SMEM_G0);
    cudaFuncSetAttribute(gemm_out2, cudaFuncAttributeMaxDynamicSharedMemorySize, SMEM_G1);
    cudaFuncSetAttribute(rec_mma,  cudaFuncAttributeMaxDynamicSharedMemorySize, SMEM_REC_BYTES);

    prep_bias<<<4, 256>>>(bi, bh);
    prep_transpose_bf<<<dim3(32, 32), 256>>>(Wi);
    prep_transpose_f16<1><<<dim3(32, 32), 256>>>(Wo);
    prep_transpose_f16<2><<<dim3(32, 32), 256>>>(Wh);
    prep_h0<<<64, 256>>>(hidden0);
    prep_gather<<<8192, 256>>>(input, emb);

    gemm_ix<<<dim3(8, 128), 256, SMEM_G0>>>();
    rec_mma<<<NCTA, 256, SMEM_REC_BYTES>>>(hid_out);
    gemm_out2<<<dim3(8, 128), 256, SMEM_G1>>>(bo, out);
}